// round 12
// baseline (speedup 1.0000x reference)
#include <cuda_runtime.h>
#include <cuda_fp16.h>
#include <math.h>
#include <stdint.h>

// N = 64*32*32 = 65536 rows, D = 256, K = 1024
// Output layout: [loss (1), q_out (16777216), perplexity (1)]

#define NROWS   65536
#define DDIM    256
#define KCODES  1024
#define BATCH   64
#define HWSZ    1024
#define QELEMS  16777216

#define NEG_INF (-__int_as_float(0x7f800000))
#define IMAX    0x7FFFFFFF
#define JAX_PARTITIONABLE 1

// ---------------- scratch (device globals; no allocation allowed) ----------------
__device__ __half g_Xh[(size_t)NROWS * DDIM];          // fp16(x)     (32 MB)
__device__ __half g_Eh[(size_t)KCODES * DDIM];
__device__ __half g_Sh[(size_t)NROWS * KCODES];        // logits fp16 (128 MB)
__device__ float g_bnorm[KCODES];
__device__ float g_counts[KCODES];
__device__ float g_entrow[NROWS];
__device__ int   g_idx[NROWS];

// ---------------- helpers ----------------
__device__ __forceinline__ uint32_t smem_u32(const void* p) {
    uint32_t a;
    asm("{ .reg .u64 t; cvta.to.shared.u64 t, %1; cvt.u32.u64 %0, t; }" : "=r"(a) : "l"(p));
    return a;
}
__device__ __forceinline__ void ldsm4(uint32_t* r, const void* p) {
    uint32_t addr = smem_u32(p);
    asm volatile("ldmatrix.sync.aligned.m8n8.x4.shared.b16 {%0,%1,%2,%3}, [%4];"
        : "=r"(r[0]), "=r"(r[1]), "=r"(r[2]), "=r"(r[3]) : "r"(addr));
}
__device__ __forceinline__ void mma_f16(float* c, const uint32_t* a, uint32_t b0, uint32_t b1) {
    asm("mma.sync.aligned.m16n8k16.row.col.f32.f16.f16.f32 "
        "{%0,%1,%2,%3}, {%4,%5,%6,%7}, {%8,%9}, {%0,%1,%2,%3};"
        : "+f"(c[0]), "+f"(c[1]), "+f"(c[2]), "+f"(c[3])
        : "r"(a[0]), "r"(a[1]), "r"(a[2]), "r"(a[3]), "r"(b0), "r"(b1));
}
__device__ __forceinline__ void cpa16(uint32_t s, const void* g) {
    asm volatile("cp.async.ca.shared.global [%0], [%1], 16;" :: "r"(s), "l"(g));
}
#define CPA_COMMIT() asm volatile("cp.async.commit_group;" ::: "memory")
#define CPA_WAIT1()  asm volatile("cp.async.wait_group 1;" ::: "memory")

// ---------------- threefry2x32 (JAX-exact, validated R4/R6-R11) ----------------
__device__ __forceinline__ void threefry2x32(unsigned int x0, unsigned int x1,
                                             unsigned int& r0, unsigned int& r1) {
    const unsigned int k0 = 0u, k1 = 42u;
    const unsigned int k2 = 0u ^ 42u ^ 0x1BD11BDAu;
#define TFR(r) { x0 += x1; x1 = __funnelshift_l(x1, x1, r); x1 ^= x0; }
    x0 += k0; x1 += k1;
    TFR(13) TFR(15) TFR(26) TFR(6)
    x0 += k1; x1 += k2 + 1u;
    TFR(17) TFR(29) TFR(16) TFR(24)
    x0 += k2; x1 += k0 + 2u;
    TFR(13) TFR(15) TFR(26) TFR(6)
    x0 += k0; x1 += k1 + 3u;
    TFR(17) TFR(29) TFR(16) TFR(24)
    x0 += k1; x1 += k2 + 4u;
    TFR(13) TFR(15) TFR(26) TFR(6)
    x0 += k2; x1 += k0 + 5u;
#undef TFR
    r0 = x0; r1 = x1;
}
__device__ __forceinline__ unsigned int rbits_at(unsigned int e) {
#if JAX_PARTITIONABLE
    unsigned int r0, r1;
    threefry2x32(0u, e, r0, r1);
    return r0 ^ r1;
#else
    const unsigned int NH = (NROWS * (unsigned)KCODES) / 2u;
    unsigned int p = (e < NH) ? e : (e - NH);
    unsigned int r0, r1;
    threefry2x32(p, p + NH, r0, r1);
    return (e < NH) ? r0 : r1;
#endif
}
__device__ __forceinline__ float gumbel_exact(unsigned int e) {
    unsigned int bits = rbits_at(e);
    float f = __uint_as_float((bits >> 9) | 0x3f800000u) - 1.0f;
    float u = fmaxf(1e-9f, f + 1e-9f);
    return -logf(-logf(u));
}
__device__ __forceinline__ float gumbel_fast(unsigned int e) {
    unsigned int bits = rbits_at(e);
    float f = __uint_as_float((bits >> 9) | 0x3f800000u) - 1.0f;
    float u = fmaxf(1e-9f, f + 1e-9f);
    float v;
    if (f > 0.996f) v = -logf(u);     // near u=1: cancellation -> exact (rare)
    else            v = -__logf(u);
    return -__logf(v);
}

// ---------------- kernel 1: transpose + fp16 convert ----------------
__global__ void transpose_kernel(const float* __restrict__ in) {
    __shared__ float tile[32][33];
    int b   = blockIdx.z;
    int hw0 = blockIdx.x * 32;
    int d0  = blockIdx.y * 32;
    int tx = threadIdx.x, ty = threadIdx.y;
    const float* src = in + (size_t)b * (DDIM * HWSZ);
#pragma unroll
    for (int j = 0; j < 4; j++) {
        int d  = d0 + ty + j * 8;
        int hw = hw0 + tx;
        tile[ty + j * 8][tx] = src[(size_t)d * HWSZ + hw];
    }
    __syncthreads();
#pragma unroll
    for (int j = 0; j < 4; j++) {
        int hw = hw0 + ty + j * 8;
        int d  = d0 + tx;
        g_Xh[(size_t)(b * HWSZ + hw) * DDIM + d] = __float2half_rn(tile[tx][ty + j * 8]);
    }
}

// ---------------- kernel 2: embedding norms + fp16 + zero counts ----------------
__global__ void prep_e_kernel(const float* __restrict__ E) {
    __shared__ float red[256];
    int k = blockIdx.x, t = threadIdx.x;
    float v = E[(size_t)k * DDIM + t];
    g_Eh[(size_t)k * DDIM + t] = __float2half_rn(v);
    red[t] = v * v;
    __syncthreads();
    for (int off = 128; off > 0; off >>= 1) {
        if (t < off) red[t] += red[t + off];
        __syncthreads();
    }
    if (t == 0) { g_bnorm[k] = red[0]; g_counts[k] = 0.0f; }
}

// ---------------- kernel 3: fp16 mma.sync GEMM, cp.async 3-stage, fp16 S out ----------------
#define LDS_ROW 40
#define TILE_ELEMS (128 * LDS_ROW)
#define TILE_BYTES (TILE_ELEMS * 2)
#define NSTAGE 3
#define SMEM_DYN (512 + NSTAGE * 2 * TILE_BYTES)    // 61952

__device__ __forceinline__ void issue_stage(uint32_t s_tiles_u32, int buf, int m0, int n0, int d0) {
    int tid = threadIdx.x;
    uint32_t base = s_tiles_u32 + (uint32_t)buf * 2 * TILE_BYTES;
#pragma unroll
    for (int q = 0; q < 2; q++) {
        int idx = tid + 256 * q;
        int row = idx >> 2, quad = idx & 3;
        uint32_t soff = (uint32_t)(row * LDS_ROW + quad * 8) * 2;
        size_t ga = (size_t)(m0 + row) * DDIM + d0 + quad * 8;
        size_t gb = (size_t)(n0 + row) * DDIM + d0 + quad * 8;
        cpa16(base + 0 * TILE_BYTES + soff, g_Xh + ga);
        cpa16(base + 1 * TILE_BYTES + soff, g_Eh + gb);
    }
}

__global__ __launch_bounds__(256, 2) void gemm_f16_kernel() {
    extern __shared__ char smem[];
    float* s_bn = (float*)smem;
    __half* s_tiles = (__half*)(smem + 512);
    uint32_t s_tiles_u32 = smem_u32(s_tiles);
#define TILE_PTR(st, a) (s_tiles + ((st) * 2 + (a)) * TILE_ELEMS)

    int tid = threadIdx.x, wid = tid >> 5, lane = tid & 31;
    int warp_m = wid & 3, warp_n = wid >> 2;
    int n0 = blockIdx.x * 128;
    int m0 = blockIdx.y * 128;

    if (tid < 128) s_bn[tid] = g_bnorm[n0 + tid];

    float acc[2][8][4];
#pragma unroll
    for (int i = 0; i < 2; i++)
#pragma unroll
        for (int j = 0; j < 8; j++)
#pragma unroll
            for (int q = 0; q < 4; q++) acc[i][j][q] = 0.0f;

    issue_stage(s_tiles_u32, 0, m0, n0, 0);
    CPA_COMMIT();
    issue_stage(s_tiles_u32, 1, m0, n0, 32);
    CPA_COMMIT();

    int a_row = warp_m * 32 + (lane & 15);
    int b_row = warp_n * 64 + (lane & 15);
    int k_off = (lane >> 4) * 8;

    for (int c = 0; c < 8; c++) {
        CPA_WAIT1();
        __syncthreads();
        if (c + 2 < 8) {
            issue_stage(s_tiles_u32, (c + 2) % NSTAGE, m0, n0, (c + 2) * 32);
            CPA_COMMIT();
        }
        int st = c % NSTAGE;
        const __half* At = TILE_PTR(st, 0);
        const __half* Bt = TILE_PTR(st, 1);
#pragma unroll
        for (int ks = 0; ks < 2; ks++) {
            int kc = ks * 16 + k_off;
            uint32_t fA[2][4];
#pragma unroll
            for (int mt = 0; mt < 2; mt++)
                ldsm4(fA[mt], At + (a_row + mt * 16) * LDS_ROW + kc);
#pragma unroll
            for (int bt = 0; bt < 4; bt++) {
                uint32_t fB[4];
                ldsm4(fB, Bt + (b_row + bt * 16) * LDS_ROW + kc);
                mma_f16(acc[0][2 * bt],     fA[0], fB[0], fB[2]);
                mma_f16(acc[1][2 * bt],     fA[1], fB[0], fB[2]);
                mma_f16(acc[0][2 * bt + 1], fA[0], fB[1], fB[3]);
                mma_f16(acc[1][2 * bt + 1], fA[1], fB[1], fB[3]);
            }
        }
    }

    // epilogue: s = 2*acc - bnorm -> fp16
    int g = lane >> 2, tg = lane & 3;
#pragma unroll
    for (int mi = 0; mi < 2; mi++) {
        int r0 = m0 + warp_m * 32 + mi * 16 + g;
#pragma unroll
        for (int ni = 0; ni < 8; ni++) {
            int cl = warp_n * 64 + ni * 8 + tg * 2;
            float bn0 = s_bn[cl], bn1 = s_bn[cl + 1];
            float2 o0 = { fmaf(2.0f, acc[mi][ni][0], -bn0), fmaf(2.0f, acc[mi][ni][1], -bn1) };
            float2 o1 = { fmaf(2.0f, acc[mi][ni][2], -bn0), fmaf(2.0f, acc[mi][ni][3], -bn1) };
            *(__half2*)&g_Sh[(size_t)r0 * KCODES + n0 + cl] = __float22half2_rn(o0);
            *(__half2*)&g_Sh[(size_t)(r0 + 8) * KCODES + n0 + cl] = __float22half2_rn(o1);
        }
    }
#undef TILE_PTR
}

// ---------------- top-3 insert ----------------
__device__ __forceinline__ void ins3(float v, int i,
                                     float& v1, int& i1, float& v2, int& i2, float& v3, int& i3) {
    if (v > v1 || (v == v1 && i < i1))      { v3 = v2; i3 = i2; v2 = v1; i2 = i1; v1 = v; i1 = i; }
    else if (v > v2 || (v == v2 && i < i2)) { v3 = v2; i3 = i2; v2 = v; i2 = i; }
    else if (v > v3 || (v == v3 && i < i3)) { v3 = v; i3 = i; }
}

// ---------------- kernel 4: per-row softmax-entropy + gumbel top-3 argmax ----------------
__global__ __launch_bounds__(256)
void epi_kernel(const float* __restrict__ inp, const float* __restrict__ emb) {
    int n = blockIdx.x;
    int t = threadIdx.x;
    int lane = t & 31, wid = t >> 5;

    uint2 u2 = ((const uint2*)(g_Sh + (size_t)n * KCODES))[t];
    float2 f0 = __half22float2(*(__half2*)&u2.x);
    float2 f1 = __half22float2(*(__half2*)&u2.y);
    float svv[4] = {f0.x, f0.y, f1.x, f1.y};

    float v1 = NEG_INF, v2 = NEG_INF, v3 = NEG_INF;
    int   i1 = IMAX, i2 = IMAX, i3 = IMAX;
    float smax = NEG_INF;
#pragma unroll
    for (int jj = 0; jj < 4; jj++) {
        int k = t * 4 + jj;
        float y = svv[jj] + gumbel_fast((unsigned)n * (unsigned)KCODES + (unsigned)k);
        ins3(y, k, v1, i1, v2, i2, v3, i3);
        smax = fmaxf(smax, svv[jj]);
    }

#pragma unroll
    for (int off = 16; off > 0; off >>= 1) {
        float b1 = __shfl_down_sync(0xFFFFFFFFu, v1, off);
        int  bi1 = __shfl_down_sync(0xFFFFFFFFu, i1, off);
        float b2 = __shfl_down_sync(0xFFFFFFFFu, v2, off);
        int  bi2 = __shfl_down_sync(0xFFFFFFFFu, i2, off);
        float b3 = __shfl_down_sync(0xFFFFFFFFu, v3, off);
        int  bi3 = __shfl_down_sync(0xFFFFFFFFu, i3, off);
        smax = fmaxf(smax, __shfl_down_sync(0xFFFFFFFFu, smax, off));
        ins3(b1, bi1, v1, i1, v2, i2, v3, i3);
        ins3(b2, bi2, v1, i1, v2, i2, v3, i3);
        ins3(b3, bi3, v1, i1, v2, i2, v3, i3);
    }

    __shared__ float wv1[8], wv2[8], wv3[8];
    __shared__ int   wi1[8], wi2[8], wi3[8];
    __shared__ float wmx[8], wz[8], ww[8];
    __shared__ int   s_i1, s_i2, s_i3;
    __shared__ float s_gap, s_max;
    __shared__ double rd1[256], rd2[256], rd3[256];

    if (lane == 0) {
        wv1[wid] = v1; wi1[wid] = i1; wv2[wid] = v2; wi2[wid] = i2;
        wv3[wid] = v3; wi3[wid] = i3; wmx[wid] = smax;
    }
    __syncthreads();

    if (wid == 0) {
        float a1 = (lane < 8) ? wv1[lane] : NEG_INF;
        int  ai1 = (lane < 8) ? wi1[lane] : IMAX;
        float a2 = (lane < 8) ? wv2[lane] : NEG_INF;
        int  ai2 = (lane < 8) ? wi2[lane] : IMAX;
        float a3 = (lane < 8) ? wv3[lane] : NEG_INF;
        int  ai3 = (lane < 8) ? wi3[lane] : IMAX;
        float mx = (lane < 8) ? wmx[lane] : NEG_INF;
#pragma unroll
        for (int off = 4; off > 0; off >>= 1) {
            float b1 = __shfl_down_sync(0xFFFFFFFFu, a1, off);
            int  bi1 = __shfl_down_sync(0xFFFFFFFFu, ai1, off);
            float b2 = __shfl_down_sync(0xFFFFFFFFu, a2, off);
            int  bi2 = __shfl_down_sync(0xFFFFFFFFu, ai2, off);
            float b3 = __shfl_down_sync(0xFFFFFFFFu, a3, off);
            int  bi3 = __shfl_down_sync(0xFFFFFFFFu, ai3, off);
            mx = fmaxf(mx, __shfl_down_sync(0xFFFFFFFFu, mx, off));
            ins3(b1, bi1, a1, ai1, a2, ai2, a3, ai3);
            ins3(b2, bi2, a1, ai1, a2, ai2, a3, ai3);
            ins3(b3, bi3, a1, ai1, a2, ai2, a3, ai3);
        }
        if (lane == 0) {
            s_i1 = ai1; s_i2 = ai2; s_i3 = ai3;
            s_gap = a1 - a2; s_max = mx;
        }
    }
    __syncthreads();

    int bidx = s_i1;
    // fp64 + exact-gumbel refinement of top-3 near ties (covers fp16 S + fp16 mma noise)
    if (s_gap < 0.02f) {
        int b = n >> 10, hw = n & 1023;
        float xd = inp[(size_t)b * (DDIM * HWSZ) + (size_t)t * HWSZ + hw];
        float e1 = emb[(size_t)s_i1 * DDIM + t];
        float e2 = emb[(size_t)s_i2 * DDIM + t];
        float e3 = emb[(size_t)s_i3 * DDIM + t];
        rd1[t] = 2.0 * (double)xd * (double)e1 - (double)e1 * (double)e1;
        rd2[t] = 2.0 * (double)xd * (double)e2 - (double)e2 * (double)e2;
        rd3[t] = 2.0 * (double)xd * (double)e3 - (double)e3 * (double)e3;
        __syncthreads();
        for (int off = 128; off > 0; off >>= 1) {
            if (t < off) { rd1[t] += rd1[t + off]; rd2[t] += rd2[t + off]; rd3[t] += rd3[t + off]; }
            __syncthreads();
        }
        if (t == 0) {
            double ya = rd1[0] + (double)gumbel_exact((unsigned)n * (unsigned)KCODES + (unsigned)s_i1);
            double yb = rd2[0] + (double)gumbel_exact((unsigned)n * (unsigned)KCODES + (unsigned)s_i2);
            double yc = rd3[0] + (double)gumbel_exact((unsigned)n * (unsigned)KCODES + (unsigned)s_i3);
            double bv = ya; int bi = s_i1;
            if (yb > bv || (yb == bv && s_i2 < bi)) { bv = yb; bi = s_i2; }
            if (yc > bv || (yc == bv && s_i3 < bi)) { bv = yc; bi = s_i3; }
            bidx = bi;
        }
        __syncthreads();
    }

    float mrow = s_max;
    float z = 0.0f, w = 0.0f;
#pragma unroll
    for (int jj = 0; jj < 4; jj++) {
        float d = svv[jj] - mrow;
        float e = __expf(d);
        z += e;
        w += d * e;
    }
#pragma unroll
    for (int off = 16; off > 0; off >>= 1) {
        z += __shfl_down_sync(0xFFFFFFFFu, z, off);
        w += __shfl_down_sync(0xFFFFFFFFu, w, off);
    }
    if (lane == 0) { wz[wid] = z; ww[wid] = w; }
    __syncthreads();
    if (t == 0) {
        float Z = 0.0f, W = 0.0f;
#pragma unroll
        for (int q = 0; q < 8; q++) { Z += wz[q]; W += ww[q]; }
        g_entrow[n] = W / Z - logf(Z);
        g_idx[n] = bidx;
        atomicAdd(&g_counts[bidx], 1.0f);
    }
}

// ---------------- kernel 5: scatter q_out = embedding[idx] ----------------
__global__ __launch_bounds__(256)
void scatter_kernel(const float* __restrict__ E, float* __restrict__ qout) {
    int b  = blockIdx.y;
    int hw = blockIdx.x * 256 + threadIdx.x;
    int n  = b * HWSZ + hw;
    int row = g_idx[n];
    const float4* e4 = reinterpret_cast<const float4*>(E + (size_t)row * DDIM);
    float* outb = qout + (size_t)b * (DDIM * HWSZ) + hw;
#pragma unroll 4
    for (int d4 = 0; d4 < DDIM / 4; d4++) {
        float4 v = e4[d4];
        outb[(size_t)(d4 * 4 + 0) * HWSZ] = v.x;
        outb[(size_t)(d4 * 4 + 1) * HWSZ] = v.y;
        outb[(size_t)(d4 * 4 + 2) * HWSZ] = v.z;
        outb[(size_t)(d4 * 4 + 3) * HWSZ] = v.w;
    }
}

// ---------------- kernel 6: finalize ----------------
__global__ __launch_bounds__(1024)
void finalize_kernel(float* __restrict__ out) {
    __shared__ double sh1[1024];
    __shared__ double sh2[1024];
    int t = threadIdx.x;
    double es = 0.0;
    for (int j = 0; j < NROWS / 1024; j++) es += (double)g_entrow[t + 1024 * j];
    float c = g_counts[t];
    float q = c * (1.0f / (float)NROWS);
    float term = q * logf(q + 1e-10f);
    sh1[t] = es;
    sh2[t] = (double)term;
    __syncthreads();
    for (int off = 512; off > 0; off >>= 1) {
        if (t < off) { sh1[t] += sh1[t + off]; sh2[t] += sh2[t + off]; }
        __syncthreads();
    }
    if (t == 0) {
        out[0] = 0.25f * (float)(sh1[0] / (double)NROWS);
        out[1 + QELEMS] = expf(-(float)sh2[0]);
    }
}

// ---------------- launch: single stream ----------------
extern "C" void kernel_launch(void* const* d_in, const int* in_sizes, int n_in,
                              void* d_out, int out_size) {
    const float* inp = (const float*)d_in[0];
    const float* emb = (const float*)d_in[1];
    float* out = (float*)d_out;

    cudaFuncSetAttribute(gemm_f16_kernel, cudaFuncAttributeMaxDynamicSharedMemorySize, SMEM_DYN);

    transpose_kernel<<<dim3(HWSZ / 32, DDIM / 32, BATCH), dim3(32, 8)>>>(inp);
    prep_e_kernel<<<KCODES, 256>>>(emb);
    gemm_f16_kernel<<<dim3(KCODES / 128, NROWS / 128), 256, SMEM_DYN>>>();
    epi_kernel<<<NROWS, 256>>>(inp, emb);
    scatter_kernel<<<dim3(HWSZ / 256, BATCH), 256>>>(emb, out + 1);
    finalize_kernel<<<1, 1024>>>(out);
}

// round 13
// speedup vs baseline: 1.0431x; 1.0431x over previous
#include <cuda_runtime.h>
#include <cuda_fp16.h>
#include <math.h>
#include <stdint.h>

// N = 64*32*32 = 65536 rows, D = 256, K = 1024
// Output layout: [loss (1), q_out (16777216), perplexity (1)]

#define NROWS   65536
#define DDIM    256
#define KCODES  1024
#define BATCH   64
#define HWSZ    1024
#define QELEMS  16777216

#define NEG_INF (-__int_as_float(0x7f800000))
#define IMAX    0x7FFFFFFF
#define JAX_PARTITIONABLE 1

// ---------------- scratch (device globals; no allocation allowed) ----------------
__device__ __half g_Xh[(size_t)NROWS * DDIM];          // fp16(x)     (32 MB)
__device__ __half g_Eh[(size_t)KCODES * DDIM];
__device__ __half g_Sh[(size_t)NROWS * KCODES];        // logits fp16 (128 MB)
__device__ float g_bnorm[KCODES];
__device__ float g_counts[KCODES];
__device__ float g_entrow[NROWS];
__device__ int   g_idx[NROWS];

// ---------------- helpers ----------------
__device__ __forceinline__ uint32_t smem_u32(const void* p) {
    uint32_t a;
    asm("{ .reg .u64 t; cvta.to.shared.u64 t, %1; cvt.u32.u64 %0, t; }" : "=r"(a) : "l"(p));
    return a;
}
__device__ __forceinline__ void ldsm4(uint32_t* r, const void* p) {
    uint32_t addr = smem_u32(p);
    asm volatile("ldmatrix.sync.aligned.m8n8.x4.shared.b16 {%0,%1,%2,%3}, [%4];"
        : "=r"(r[0]), "=r"(r[1]), "=r"(r[2]), "=r"(r[3]) : "r"(addr));
}
__device__ __forceinline__ void mma_f16(float* c, const uint32_t* a, uint32_t b0, uint32_t b1) {
    asm("mma.sync.aligned.m16n8k16.row.col.f32.f16.f16.f32 "
        "{%0,%1,%2,%3}, {%4,%5,%6,%7}, {%8,%9}, {%0,%1,%2,%3};"
        : "+f"(c[0]), "+f"(c[1]), "+f"(c[2]), "+f"(c[3])
        : "r"(a[0]), "r"(a[1]), "r"(a[2]), "r"(a[3]), "r"(b0), "r"(b1));
}
__device__ __forceinline__ void cpa16(uint32_t s, const void* g) {
    asm volatile("cp.async.ca.shared.global [%0], [%1], 16;" :: "r"(s), "l"(g));
}
#define CPA_COMMIT() asm volatile("cp.async.commit_group;" ::: "memory")
#define CPA_WAIT1()  asm volatile("cp.async.wait_group 1;" ::: "memory")

// ---------------- threefry2x32 (JAX-exact, validated R4/R6-R12) ----------------
__device__ __forceinline__ void threefry2x32(unsigned int x0, unsigned int x1,
                                             unsigned int& r0, unsigned int& r1) {
    const unsigned int k0 = 0u, k1 = 42u;
    const unsigned int k2 = 0u ^ 42u ^ 0x1BD11BDAu;
#define TFR(r) { x0 += x1; x1 = __funnelshift_l(x1, x1, r); x1 ^= x0; }
    x0 += k0; x1 += k1;
    TFR(13) TFR(15) TFR(26) TFR(6)
    x0 += k1; x1 += k2 + 1u;
    TFR(17) TFR(29) TFR(16) TFR(24)
    x0 += k2; x1 += k0 + 2u;
    TFR(13) TFR(15) TFR(26) TFR(6)
    x0 += k0; x1 += k1 + 3u;
    TFR(17) TFR(29) TFR(16) TFR(24)
    x0 += k1; x1 += k2 + 4u;
    TFR(13) TFR(15) TFR(26) TFR(6)
    x0 += k2; x1 += k0 + 5u;
#undef TFR
    r0 = x0; r1 = x1;
}
__device__ __forceinline__ unsigned int rbits_at(unsigned int e) {
#if JAX_PARTITIONABLE
    unsigned int r0, r1;
    threefry2x32(0u, e, r0, r1);
    return r0 ^ r1;
#else
    const unsigned int NH = (NROWS * (unsigned)KCODES) / 2u;
    unsigned int p = (e < NH) ? e : (e - NH);
    unsigned int r0, r1;
    threefry2x32(p, p + NH, r0, r1);
    return (e < NH) ? r0 : r1;
#endif
}
// exact version: reference-grade (refinement only; bit-matched 6 passing rounds)
__device__ __forceinline__ float gumbel_exact(unsigned int e) {
    unsigned int bits = rbits_at(e);
    float f = __uint_as_float((bits >> 9) | 0x3f800000u) - 1.0f;
    float u = fmaxf(1e-9f, f + 1e-9f);
    return -logf(-logf(u));
}
// scan version: branchless, ~1e-5 abs accuracy; errors covered by the
// fp64 + exact-gumbel top-3 refinement (threshold 0.02).
__device__ __forceinline__ float gumbel_scan(unsigned int e) {
    unsigned int bits = rbits_at(e);
    float f = __uint_as_float((bits >> 9) | 0x3f800000u) - 1.0f;  // [0,1), exact
    float u = f + 1e-9f;
    // w = -ln(u)/ln2 = -log2(u); near u->1 use series in dd = (1-f)-1e-9 (exact subtract)
    float w_fast = -__log2f(u);
    float dd = (1.0f - f) - 1e-9f;
    float w_ser = dd * fmaf(dd, fmaf(dd, 0.48089835f, 0.72134752f), 1.4426950f);
    float w = (f > 0.996f) ? w_ser : w_fast;
    // g = -ln(ln2 * w) = -ln2*log2(w) - ln(ln2)
    return fmaf(-0.69314718f, __log2f(w), 0.36651292f);
}

// ---------------- kernel 1: transpose + fp16 convert ----------------
__global__ void transpose_kernel(const float* __restrict__ in) {
    __shared__ float tile[32][33];
    int b   = blockIdx.z;
    int hw0 = blockIdx.x * 32;
    int d0  = blockIdx.y * 32;
    int tx = threadIdx.x, ty = threadIdx.y;
    const float* src = in + (size_t)b * (DDIM * HWSZ);
#pragma unroll
    for (int j = 0; j < 4; j++) {
        int d  = d0 + ty + j * 8;
        int hw = hw0 + tx;
        tile[ty + j * 8][tx] = src[(size_t)d * HWSZ + hw];
    }
    __syncthreads();
#pragma unroll
    for (int j = 0; j < 4; j++) {
        int hw = hw0 + ty + j * 8;
        int d  = d0 + tx;
        g_Xh[(size_t)(b * HWSZ + hw) * DDIM + d] = __float2half_rn(tile[tx][ty + j * 8]);
    }
}

// ---------------- kernel 2: embedding norms + fp16 + zero counts ----------------
__global__ void prep_e_kernel(const float* __restrict__ E) {
    __shared__ float red[256];
    int k = blockIdx.x, t = threadIdx.x;
    float v = E[(size_t)k * DDIM + t];
    g_Eh[(size_t)k * DDIM + t] = __float2half_rn(v);
    red[t] = v * v;
    __syncthreads();
    for (int off = 128; off > 0; off >>= 1) {
        if (t < off) red[t] += red[t + off];
        __syncthreads();
    }
    if (t == 0) { g_bnorm[k] = red[0]; g_counts[k] = 0.0f; }
}

// ---------------- kernel 3: fp16 mma.sync GEMM, cp.async 3-stage, fp16 S out ----------------
#define LDS_ROW 40
#define TILE_ELEMS (128 * LDS_ROW)
#define TILE_BYTES (TILE_ELEMS * 2)
#define NSTAGE 3
#define SMEM_DYN (512 + NSTAGE * 2 * TILE_BYTES)    // 61952

__device__ __forceinline__ void issue_stage(uint32_t s_tiles_u32, int buf, int m0, int n0, int d0) {
    int tid = threadIdx.x;
    uint32_t base = s_tiles_u32 + (uint32_t)buf * 2 * TILE_BYTES;
#pragma unroll
    for (int q = 0; q < 2; q++) {
        int idx = tid + 256 * q;
        int row = idx >> 2, quad = idx & 3;
        uint32_t soff = (uint32_t)(row * LDS_ROW + quad * 8) * 2;
        size_t ga = (size_t)(m0 + row) * DDIM + d0 + quad * 8;
        size_t gb = (size_t)(n0 + row) * DDIM + d0 + quad * 8;
        cpa16(base + 0 * TILE_BYTES + soff, g_Xh + ga);
        cpa16(base + 1 * TILE_BYTES + soff, g_Eh + gb);
    }
}

__global__ __launch_bounds__(256, 2) void gemm_f16_kernel() {
    extern __shared__ char smem[];
    float* s_bn = (float*)smem;
    __half* s_tiles = (__half*)(smem + 512);
    uint32_t s_tiles_u32 = smem_u32(s_tiles);
#define TILE_PTR(st, a) (s_tiles + ((st) * 2 + (a)) * TILE_ELEMS)

    int tid = threadIdx.x, wid = tid >> 5, lane = tid & 31;
    int warp_m = wid & 3, warp_n = wid >> 2;
    int n0 = blockIdx.x * 128;
    int m0 = blockIdx.y * 128;

    if (tid < 128) s_bn[tid] = g_bnorm[n0 + tid];

    float acc[2][8][4];
#pragma unroll
    for (int i = 0; i < 2; i++)
#pragma unroll
        for (int j = 0; j < 8; j++)
#pragma unroll
            for (int q = 0; q < 4; q++) acc[i][j][q] = 0.0f;

    issue_stage(s_tiles_u32, 0, m0, n0, 0);
    CPA_COMMIT();
    issue_stage(s_tiles_u32, 1, m0, n0, 32);
    CPA_COMMIT();

    int a_row = warp_m * 32 + (lane & 15);
    int b_row = warp_n * 64 + (lane & 15);
    int k_off = (lane >> 4) * 8;

    for (int c = 0; c < 8; c++) {
        CPA_WAIT1();
        __syncthreads();
        if (c + 2 < 8) {
            issue_stage(s_tiles_u32, (c + 2) % NSTAGE, m0, n0, (c + 2) * 32);
            CPA_COMMIT();
        }
        int st = c % NSTAGE;
        const __half* At = TILE_PTR(st, 0);
        const __half* Bt = TILE_PTR(st, 1);
#pragma unroll
        for (int ks = 0; ks < 2; ks++) {
            int kc = ks * 16 + k_off;
            uint32_t fA[2][4];
#pragma unroll
            for (int mt = 0; mt < 2; mt++)
                ldsm4(fA[mt], At + (a_row + mt * 16) * LDS_ROW + kc);
#pragma unroll
            for (int bt = 0; bt < 4; bt++) {
                uint32_t fB[4];
                ldsm4(fB, Bt + (b_row + bt * 16) * LDS_ROW + kc);
                mma_f16(acc[0][2 * bt],     fA[0], fB[0], fB[2]);
                mma_f16(acc[1][2 * bt],     fA[1], fB[0], fB[2]);
                mma_f16(acc[0][2 * bt + 1], fA[0], fB[1], fB[3]);
                mma_f16(acc[1][2 * bt + 1], fA[1], fB[1], fB[3]);
            }
        }
    }

    // epilogue: s = 2*acc - bnorm -> fp16
    int g = lane >> 2, tg = lane & 3;
#pragma unroll
    for (int mi = 0; mi < 2; mi++) {
        int r0 = m0 + warp_m * 32 + mi * 16 + g;
#pragma unroll
        for (int ni = 0; ni < 8; ni++) {
            int cl = warp_n * 64 + ni * 8 + tg * 2;
            float bn0 = s_bn[cl], bn1 = s_bn[cl + 1];
            float2 o0 = { fmaf(2.0f, acc[mi][ni][0], -bn0), fmaf(2.0f, acc[mi][ni][1], -bn1) };
            float2 o1 = { fmaf(2.0f, acc[mi][ni][2], -bn0), fmaf(2.0f, acc[mi][ni][3], -bn1) };
            *(__half2*)&g_Sh[(size_t)r0 * KCODES + n0 + cl] = __float22half2_rn(o0);
            *(__half2*)&g_Sh[(size_t)(r0 + 8) * KCODES + n0 + cl] = __float22half2_rn(o1);
        }
    }
#undef TILE_PTR
}

// ---------------- top-3 insert (reductions only; tie-break aware) ----------------
__device__ __forceinline__ void ins3(float v, int i,
                                     float& v1, int& i1, float& v2, int& i2, float& v3, int& i3) {
    if (v > v1 || (v == v1 && i < i1))      { v3 = v2; i3 = i2; v2 = v1; i2 = i1; v1 = v; i1 = i; }
    else if (v > v2 || (v == v2 && i < i2)) { v3 = v2; i3 = i2; v2 = v; i2 = i; }
    else if (v > v3 || (v == v3 && i < i3)) { v3 = v; i3 = i; }
}

// ---------------- kernel 4: per-row softmax-entropy + gumbel top-3 argmax ----------------
__global__ __launch_bounds__(256)
void epi_kernel(const float* __restrict__ inp, const float* __restrict__ emb) {
    int n = blockIdx.x;
    int t = threadIdx.x;
    int lane = t & 31, wid = t >> 5;

    uint2 u2 = ((const uint2*)(g_Sh + (size_t)n * KCODES))[t];
    float2 f0 = __half22float2(*(__half2*)&u2.x);
    float2 f1 = __half22float2(*(__half2*)&u2.y);
    float svv[4] = {f0.x, f0.y, f1.x, f1.y};

    float v1 = NEG_INF, v2 = NEG_INF, v3 = NEG_INF;
    int   i1 = IMAX, i2 = IMAX, i3 = IMAX;
    float smax = NEG_INF;
    unsigned ebase = (unsigned)n * (unsigned)KCODES + (unsigned)t * 4u;
#pragma unroll
    for (int jj = 0; jj < 4; jj++) {
        int k = t * 4 + jj;
        float y = svv[jj] + gumbel_scan(ebase + (unsigned)jj);
        // branchless top-3 insert (strict >: ascending k keeps first max)
        bool c1 = y > v1;
        bool c2 = y > v2;
        bool c3 = y > v3;
        v3 = c2 ? v2 : (c3 ? y : v3);
        i3 = c2 ? i2 : (c3 ? k : i3);
        v2 = c1 ? v1 : (c2 ? y : v2);
        i2 = c1 ? i1 : (c2 ? k : i2);
        v1 = c1 ? y : v1;
        i1 = c1 ? k : i1;
        smax = fmaxf(smax, svv[jj]);
    }

#pragma unroll
    for (int off = 16; off > 0; off >>= 1) {
        float b1 = __shfl_down_sync(0xFFFFFFFFu, v1, off);
        int  bi1 = __shfl_down_sync(0xFFFFFFFFu, i1, off);
        float b2 = __shfl_down_sync(0xFFFFFFFFu, v2, off);
        int  bi2 = __shfl_down_sync(0xFFFFFFFFu, i2, off);
        float b3 = __shfl_down_sync(0xFFFFFFFFu, v3, off);
        int  bi3 = __shfl_down_sync(0xFFFFFFFFu, i3, off);
        smax = fmaxf(smax, __shfl_down_sync(0xFFFFFFFFu, smax, off));
        ins3(b1, bi1, v1, i1, v2, i2, v3, i3);
        ins3(b2, bi2, v1, i1, v2, i2, v3, i3);
        ins3(b3, bi3, v1, i1, v2, i2, v3, i3);
    }

    __shared__ float wv1[8], wv2[8], wv3[8];
    __shared__ int   wi1[8], wi2[8], wi3[8];
    __shared__ float wmx[8], wz[8], ww[8];
    __shared__ int   s_i1, s_i2, s_i3;
    __shared__ float s_gap, s_max;
    __shared__ double rd1[256], rd2[256], rd3[256];

    if (lane == 0) {
        wv1[wid] = v1; wi1[wid] = i1; wv2[wid] = v2; wi2[wid] = i2;
        wv3[wid] = v3; wi3[wid] = i3; wmx[wid] = smax;
    }
    __syncthreads();

    if (wid == 0) {
        float a1 = (lane < 8) ? wv1[lane] : NEG_INF;
        int  ai1 = (lane < 8) ? wi1[lane] : IMAX;
        float a2 = (lane < 8) ? wv2[lane] : NEG_INF;
        int  ai2 = (lane < 8) ? wi2[lane] : IMAX;
        float a3 = (lane < 8) ? wv3[lane] : NEG_INF;
        int  ai3 = (lane < 8) ? wi3[lane] : IMAX;
        float mx = (lane < 8) ? wmx[lane] : NEG_INF;
#pragma unroll
        for (int off = 4; off > 0; off >>= 1) {
            float b1 = __shfl_down_sync(0xFFFFFFFFu, a1, off);
            int  bi1 = __shfl_down_sync(0xFFFFFFFFu, ai1, off);
            float b2 = __shfl_down_sync(0xFFFFFFFFu, a2, off);
            int  bi2 = __shfl_down_sync(0xFFFFFFFFu, ai2, off);
            float b3 = __shfl_down_sync(0xFFFFFFFFu, a3, off);
            int  bi3 = __shfl_down_sync(0xFFFFFFFFu, ai3, off);
            mx = fmaxf(mx, __shfl_down_sync(0xFFFFFFFFu, mx, off));
            ins3(b1, bi1, a1, ai1, a2, ai2, a3, ai3);
            ins3(b2, bi2, a1, ai1, a2, ai2, a3, ai3);
            ins3(b3, bi3, a1, ai1, a2, ai2, a3, ai3);
        }
        if (lane == 0) {
            s_i1 = ai1; s_i2 = ai2; s_i3 = ai3;
            s_gap = a1 - a2; s_max = mx;
        }
    }
    __syncthreads();

    int bidx = s_i1;
    // fp64 + exact-gumbel refinement of top-3 near ties
    // (covers fp16 S quantization, fp16 mma noise, and gumbel_scan approx error)
    if (s_gap < 0.02f) {
        int b = n >> 10, hw = n & 1023;
        float xd = inp[(size_t)b * (DDIM * HWSZ) + (size_t)t * HWSZ + hw];
        float e1 = emb[(size_t)s_i1 * DDIM + t];
        float e2 = emb[(size_t)s_i2 * DDIM + t];
        float e3 = emb[(size_t)s_i3 * DDIM + t];
        rd1[t] = 2.0 * (double)xd * (double)e1 - (double)e1 * (double)e1;
        rd2[t] = 2.0 * (double)xd * (double)e2 - (double)e2 * (double)e2;
        rd3[t] = 2.0 * (double)xd * (double)e3 - (double)e3 * (double)e3;
        __syncthreads();
        for (int off = 128; off > 0; off >>= 1) {
            if (t < off) { rd1[t] += rd1[t + off]; rd2[t] += rd2[t + off]; rd3[t] += rd3[t + off]; }
            __syncthreads();
        }
        if (t == 0) {
            double ya = rd1[0] + (double)gumbel_exact((unsigned)n * (unsigned)KCODES + (unsigned)s_i1);
            double yb = rd2[0] + (double)gumbel_exact((unsigned)n * (unsigned)KCODES + (unsigned)s_i2);
            double yc = rd3[0] + (double)gumbel_exact((unsigned)n * (unsigned)KCODES + (unsigned)s_i3);
            double bv = ya; int bi = s_i1;
            if (yb > bv || (yb == bv && s_i2 < bi)) { bv = yb; bi = s_i2; }
            if (yc > bv || (yc == bv && s_i3 < bi)) { bv = yc; bi = s_i3; }
            bidx = bi;
        }
        __syncthreads();
    }

    float mrow = s_max;
    float z = 0.0f, w = 0.0f;
#pragma unroll
    for (int jj = 0; jj < 4; jj++) {
        float d = svv[jj] - mrow;
        float e = __expf(d);
        z += e;
        w += d * e;
    }
#pragma unroll
    for (int off = 16; off > 0; off >>= 1) {
        z += __shfl_down_sync(0xFFFFFFFFu, z, off);
        w += __shfl_down_sync(0xFFFFFFFFu, w, off);
    }
    if (lane == 0) { wz[wid] = z; ww[wid] = w; }
    __syncthreads();
    if (t == 0) {
        float Z = 0.0f, W = 0.0f;
#pragma unroll
        for (int q = 0; q < 8; q++) { Z += wz[q]; W += ww[q]; }
        g_entrow[n] = W / Z - logf(Z);
        g_idx[n] = bidx;
        atomicAdd(&g_counts[bidx], 1.0f);
    }
}

// ---------------- kernel 5: scatter q_out = embedding[idx] ----------------
__global__ __launch_bounds__(256)
void scatter_kernel(const float* __restrict__ E, float* __restrict__ qout) {
    int b  = blockIdx.y;
    int hw = blockIdx.x * 256 + threadIdx.x;
    int n  = b * HWSZ + hw;
    int row = g_idx[n];
    const float4* e4 = reinterpret_cast<const float4*>(E + (size_t)row * DDIM);
    float* outb = qout + (size_t)b * (DDIM * HWSZ) + hw;
#pragma unroll 4
    for (int d4 = 0; d4 < DDIM / 4; d4++) {
        float4 v = e4[d4];
        outb[(size_t)(d4 * 4 + 0) * HWSZ] = v.x;
        outb[(size_t)(d4 * 4 + 1) * HWSZ] = v.y;
        outb[(size_t)(d4 * 4 + 2) * HWSZ] = v.z;
        outb[(size_t)(d4 * 4 + 3) * HWSZ] = v.w;
    }
}

// ---------------- kernel 6: finalize ----------------
__global__ __launch_bounds__(1024)
void finalize_kernel(float* __restrict__ out) {
    __shared__ double sh1[1024];
    __shared__ double sh2[1024];
    int t = threadIdx.x;
    double es = 0.0;
    for (int j = 0; j < NROWS / 1024; j++) es += (double)g_entrow[t + 1024 * j];
    float c = g_counts[t];
    float q = c * (1.0f / (float)NROWS);
    float term = q * logf(q + 1e-10f);
    sh1[t] = es;
    sh2[t] = (double)term;
    __syncthreads();
    for (int off = 512; off > 0; off >>= 1) {
        if (t < off) { sh1[t] += sh1[t + off]; sh2[t] += sh2[t + off]; }
        __syncthreads();
    }
    if (t == 0) {
        out[0] = 0.25f * (float)(sh1[0] / (double)NROWS);
        out[1 + QELEMS] = expf(-(float)sh2[0]);
    }
}

// ---------------- launch: single stream ----------------
extern "C" void kernel_launch(void* const* d_in, const int* in_sizes, int n_in,
                              void* d_out, int out_size) {
    const float* inp = (const float*)d_in[0];
    const float* emb = (const float*)d_in[1];
    float* out = (float*)d_out;

    cudaFuncSetAttribute(gemm_f16_kernel, cudaFuncAttributeMaxDynamicSharedMemorySize, SMEM_DYN);

    transpose_kernel<<<dim3(HWSZ / 32, DDIM / 32, BATCH), dim3(32, 8)>>>(inp);
    prep_e_kernel<<<KCODES, 256>>>(emb);
    gemm_f16_kernel<<<dim3(KCODES / 128, NROWS / 128), 256, SMEM_DYN>>>();
    epi_kernel<<<NROWS, 256>>>(inp, emb);
    scatter_kernel<<<dim3(HWSZ / 256, BATCH), 256>>>(emb, out + 1);
    finalize_kernel<<<1, 1024>>>(out);
}

// round 14
// speedup vs baseline: 1.6454x; 1.5773x over previous
#include <cuda_runtime.h>
#include <cuda_fp16.h>
#include <math.h>
#include <stdint.h>

// N = 64*32*32 = 65536 rows, D = 256, K = 1024
// Output layout: [loss (1), q_out (16777216), perplexity (1)]

#define NROWS   65536
#define DDIM    256
#define KCODES  1024
#define BATCH   64
#define HWSZ    1024
#define QELEMS  16777216

#define NEG_INF (-__int_as_float(0x7f800000))
#define IMAX    0x7FFFFFFF
#define JAX_PARTITIONABLE 1

// ---------------- scratch (device globals; no allocation allowed) ----------------
__device__ __half g_Xh[(size_t)NROWS * DDIM];          // fp16(x)     (32 MB)
__device__ __half g_Eh[(size_t)KCODES * DDIM];
__device__ __half g_Sh[(size_t)NROWS * KCODES];        // logits fp16 (128 MB)
__device__ float g_bnorm[KCODES];
__device__ float g_counts[KCODES];
__device__ float g_entrow[NROWS];
__device__ int   g_idx[NROWS];

// ---------------- helpers ----------------
__device__ __forceinline__ uint32_t smem_u32(const void* p) {
    uint32_t a;
    asm("{ .reg .u64 t; cvta.to.shared.u64 t, %1; cvt.u32.u64 %0, t; }" : "=r"(a) : "l"(p));
    return a;
}
__device__ __forceinline__ void ldsm4(uint32_t* r, const void* p) {
    uint32_t addr = smem_u32(p);
    asm volatile("ldmatrix.sync.aligned.m8n8.x4.shared.b16 {%0,%1,%2,%3}, [%4];"
        : "=r"(r[0]), "=r"(r[1]), "=r"(r[2]), "=r"(r[3]) : "r"(addr));
}
__device__ __forceinline__ void mma_f16(float* c, const uint32_t* a, uint32_t b0, uint32_t b1) {
    asm("mma.sync.aligned.m16n8k16.row.col.f32.f16.f16.f32 "
        "{%0,%1,%2,%3}, {%4,%5,%6,%7}, {%8,%9}, {%0,%1,%2,%3};"
        : "+f"(c[0]), "+f"(c[1]), "+f"(c[2]), "+f"(c[3])
        : "r"(a[0]), "r"(a[1]), "r"(a[2]), "r"(a[3]), "r"(b0), "r"(b1));
}
__device__ __forceinline__ void cpa16(uint32_t s, const void* g) {
    asm volatile("cp.async.ca.shared.global [%0], [%1], 16;" :: "r"(s), "l"(g));
}
#define CPA_COMMIT() asm volatile("cp.async.commit_group;" ::: "memory")
#define CPA_WAIT1()  asm volatile("cp.async.wait_group 1;" ::: "memory")

// ---------------- threefry2x32 (JAX-exact, validated R4/R6-R13) ----------------
__device__ __forceinline__ void threefry2x32(unsigned int x0, unsigned int x1,
                                             unsigned int& r0, unsigned int& r1) {
    const unsigned int k0 = 0u, k1 = 42u;
    const unsigned int k2 = 0u ^ 42u ^ 0x1BD11BDAu;
#define TFR(r) { x0 += x1; x1 = __funnelshift_l(x1, x1, r); x1 ^= x0; }
    x0 += k0; x1 += k1;
    TFR(13) TFR(15) TFR(26) TFR(6)
    x0 += k1; x1 += k2 + 1u;
    TFR(17) TFR(29) TFR(16) TFR(24)
    x0 += k2; x1 += k0 + 2u;
    TFR(13) TFR(15) TFR(26) TFR(6)
    x0 += k0; x1 += k1 + 3u;
    TFR(17) TFR(29) TFR(16) TFR(24)
    x0 += k1; x1 += k2 + 4u;
    TFR(13) TFR(15) TFR(26) TFR(6)
    x0 += k2; x1 += k0 + 5u;
#undef TFR
    r0 = x0; r1 = x1;
}
__device__ __forceinline__ unsigned int rbits_at(unsigned int e) {
#if JAX_PARTITIONABLE
    unsigned int r0, r1;
    threefry2x32(0u, e, r0, r1);
    return r0 ^ r1;
#else
    const unsigned int NH = (NROWS * (unsigned)KCODES) / 2u;
    unsigned int p = (e < NH) ? e : (e - NH);
    unsigned int r0, r1;
    threefry2x32(p, p + NH, r0, r1);
    return (e < NH) ? r0 : r1;
#endif
}
// exact version: reference-grade (refinement only; bit-matched 7 passing rounds)
__device__ __forceinline__ float gumbel_exact(unsigned int e) {
    unsigned int bits = rbits_at(e);
    float f = __uint_as_float((bits >> 9) | 0x3f800000u) - 1.0f;
    float u = fmaxf(1e-9f, f + 1e-9f);
    return -logf(-logf(u));
}
// scan version: branchless, ~1e-4 abs accuracy; covered by refinement window.
__device__ __forceinline__ float gumbel_scan(unsigned int e) {
    unsigned int bits = rbits_at(e);
    float f = __uint_as_float((bits >> 9) | 0x3f800000u) - 1.0f;  // [0,1), exact
    float u = f + 1e-9f;
    float w_fast = -__log2f(u);
    float dd = (1.0f - f) - 1e-9f;
    float w_ser = dd * fmaf(dd, fmaf(dd, 0.48089835f, 0.72134752f), 1.4426950f);
    float w = (f > 0.996f) ? w_ser : w_fast;
    return fmaf(-0.69314718f, __log2f(w), 0.36651292f);   // -ln(ln2*w)
}

// ---------------- ordered-float key pack/unpack ----------------
__device__ __forceinline__ unsigned ykey(float y, int k) {
    int b = __float_as_int(y);
    unsigned ob = (unsigned)(b ^ ((b >> 31) | 0x80000000));
    return (ob & 0xFFFFFC00u) | (1023u - (unsigned)k);
}
__device__ __forceinline__ float ykey_val(unsigned key) {
    unsigned ob = key & 0xFFFFFC00u;
    int b = (ob & 0x80000000u) ? (int)(ob ^ 0x80000000u) : (int)~ob;
    return __int_as_float(b);
}

// ---------------- kernel 1: transpose + fp16 convert ----------------
__global__ void transpose_kernel(const float* __restrict__ in) {
    __shared__ float tile[32][33];
    int b   = blockIdx.z;
    int hw0 = blockIdx.x * 32;
    int d0  = blockIdx.y * 32;
    int tx = threadIdx.x, ty = threadIdx.y;
    const float* src = in + (size_t)b * (DDIM * HWSZ);
#pragma unroll
    for (int j = 0; j < 4; j++) {
        int d  = d0 + ty + j * 8;
        int hw = hw0 + tx;
        tile[ty + j * 8][tx] = src[(size_t)d * HWSZ + hw];
    }
    __syncthreads();
#pragma unroll
    for (int j = 0; j < 4; j++) {
        int hw = hw0 + ty + j * 8;
        int d  = d0 + tx;
        g_Xh[(size_t)(b * HWSZ + hw) * DDIM + d] = __float2half_rn(tile[tx][ty + j * 8]);
    }
}

// ---------------- kernel 2: embedding norms + fp16 + zero counts ----------------
__global__ void prep_e_kernel(const float* __restrict__ E) {
    __shared__ float red[256];
    int k = blockIdx.x, t = threadIdx.x;
    float v = E[(size_t)k * DDIM + t];
    g_Eh[(size_t)k * DDIM + t] = __float2half_rn(v);
    red[t] = v * v;
    __syncthreads();
    for (int off = 128; off > 0; off >>= 1) {
        if (t < off) red[t] += red[t + off];
        __syncthreads();
    }
    if (t == 0) { g_bnorm[k] = red[0]; g_counts[k] = 0.0f; }
}

// ---------------- kernel 3: fp16 mma.sync GEMM, cp.async 3-stage, fp16 S out ----------------
#define LDS_ROW 40
#define TILE_ELEMS (128 * LDS_ROW)
#define TILE_BYTES (TILE_ELEMS * 2)
#define NSTAGE 3
#define SMEM_DYN (512 + NSTAGE * 2 * TILE_BYTES)    // 61952

__device__ __forceinline__ void issue_stage(uint32_t s_tiles_u32, int buf, int m0, int n0, int d0) {
    int tid = threadIdx.x;
    uint32_t base = s_tiles_u32 + (uint32_t)buf * 2 * TILE_BYTES;
#pragma unroll
    for (int q = 0; q < 2; q++) {
        int idx = tid + 256 * q;
        int row = idx >> 2, quad = idx & 3;
        uint32_t soff = (uint32_t)(row * LDS_ROW + quad * 8) * 2;
        size_t ga = (size_t)(m0 + row) * DDIM + d0 + quad * 8;
        size_t gb = (size_t)(n0 + row) * DDIM + d0 + quad * 8;
        cpa16(base + 0 * TILE_BYTES + soff, g_Xh + ga);
        cpa16(base + 1 * TILE_BYTES + soff, g_Eh + gb);
    }
}

__global__ __launch_bounds__(256, 2) void gemm_f16_kernel() {
    extern __shared__ char smem[];
    float* s_bn = (float*)smem;
    __half* s_tiles = (__half*)(smem + 512);
    uint32_t s_tiles_u32 = smem_u32(s_tiles);
#define TILE_PTR(st, a) (s_tiles + ((st) * 2 + (a)) * TILE_ELEMS)

    int tid = threadIdx.x, wid = tid >> 5, lane = tid & 31;
    int warp_m = wid & 3, warp_n = wid >> 2;
    int n0 = blockIdx.x * 128;
    int m0 = blockIdx.y * 128;

    if (tid < 128) s_bn[tid] = g_bnorm[n0 + tid];

    float acc[2][8][4];
#pragma unroll
    for (int i = 0; i < 2; i++)
#pragma unroll
        for (int j = 0; j < 8; j++)
#pragma unroll
            for (int q = 0; q < 4; q++) acc[i][j][q] = 0.0f;

    issue_stage(s_tiles_u32, 0, m0, n0, 0);
    CPA_COMMIT();
    issue_stage(s_tiles_u32, 1, m0, n0, 32);
    CPA_COMMIT();

    int a_row = warp_m * 32 + (lane & 15);
    int b_row = warp_n * 64 + (lane & 15);
    int k_off = (lane >> 4) * 8;

    for (int c = 0; c < 8; c++) {
        CPA_WAIT1();
        __syncthreads();
        if (c + 2 < 8) {
            issue_stage(s_tiles_u32, (c + 2) % NSTAGE, m0, n0, (c + 2) * 32);
            CPA_COMMIT();
        }
        int st = c % NSTAGE;
        const __half* At = TILE_PTR(st, 0);
        const __half* Bt = TILE_PTR(st, 1);
#pragma unroll
        for (int ks = 0; ks < 2; ks++) {
            int kc = ks * 16 + k_off;
            uint32_t fA[2][4];
#pragma unroll
            for (int mt = 0; mt < 2; mt++)
                ldsm4(fA[mt], At + (a_row + mt * 16) * LDS_ROW + kc);
#pragma unroll
            for (int bt = 0; bt < 4; bt++) {
                uint32_t fB[4];
                ldsm4(fB, Bt + (b_row + bt * 16) * LDS_ROW + kc);
                mma_f16(acc[0][2 * bt],     fA[0], fB[0], fB[2]);
                mma_f16(acc[1][2 * bt],     fA[1], fB[0], fB[2]);
                mma_f16(acc[0][2 * bt + 1], fA[0], fB[1], fB[3]);
                mma_f16(acc[1][2 * bt + 1], fA[1], fB[1], fB[3]);
            }
        }
    }

    // epilogue: s = 2*acc - bnorm -> fp16
    int g = lane >> 2, tg = lane & 3;
#pragma unroll
    for (int mi = 0; mi < 2; mi++) {
        int r0 = m0 + warp_m * 32 + mi * 16 + g;
#pragma unroll
        for (int ni = 0; ni < 8; ni++) {
            int cl = warp_n * 64 + ni * 8 + tg * 2;
            float bn0 = s_bn[cl], bn1 = s_bn[cl + 1];
            float2 o0 = { fmaf(2.0f, acc[mi][ni][0], -bn0), fmaf(2.0f, acc[mi][ni][1], -bn1) };
            float2 o1 = { fmaf(2.0f, acc[mi][ni][2], -bn0), fmaf(2.0f, acc[mi][ni][3], -bn1) };
            *(__half2*)&g_Sh[(size_t)r0 * KCODES + n0 + cl] = __float22half2_rn(o0);
            *(__half2*)&g_Sh[(size_t)(r0 + 8) * KCODES + n0 + cl] = __float22half2_rn(o1);
        }
    }
#undef TILE_PTR
}

// ---------------- top-3 insert (rare refine path only) ----------------
__device__ __forceinline__ void ins3(float v, int i,
                                     float& v1, int& i1, float& v2, int& i2, float& v3, int& i3) {
    if (v > v1 || (v == v1 && i < i1))      { v3 = v2; i3 = i2; v2 = v1; i2 = i1; v1 = v; i1 = i; }
    else if (v > v2 || (v == v2 && i < i2)) { v3 = v2; i3 = i2; v2 = v; i2 = i; }
    else if (v > v3 || (v == v3 && i < i3)) { v3 = v; i3 = i; }
}

// ---------------- kernel 4: per-row softmax-entropy + packed-key gumbel argmax ----------------
__global__ __launch_bounds__(256)
void epi_kernel(const float* __restrict__ inp, const float* __restrict__ emb) {
    int n = blockIdx.x;
    int t = threadIdx.x;
    int lane = t & 31, wid = t >> 5;

    uint2 u2 = ((const uint2*)(g_Sh + (size_t)n * KCODES))[t];
    float2 f0 = __half22float2(*(__half2*)&u2.x);
    float2 f1 = __half22float2(*(__half2*)&u2.y);
    float svv[4] = {f0.x, f0.y, f1.x, f1.y};

    unsigned ebase = (unsigned)n * (unsigned)KCODES + (unsigned)t * 4u;
    unsigned keys[4];
    unsigned kmax = 0u;
    float smax = NEG_INF;
#pragma unroll
    for (int jj = 0; jj < 4; jj++) {
        float y = svv[jj] + gumbel_scan(ebase + (unsigned)jj);
        unsigned key = ykey(y, t * 4 + jj);
        keys[jj] = key;
        kmax = umax(kmax, key);
        smax = fmaxf(smax, svv[jj]);
    }

    __shared__ unsigned wk[8];
    __shared__ float wm[8], wz[8], ww[8];
    __shared__ unsigned s_key1, s_key2;
    __shared__ float s_max;
    __shared__ int   s_i1, s_i2, s_i3;
    __shared__ double rd1[256], rd2[256], rd3[256];

    // phase 1: reduce kmax + smax
#pragma unroll
    for (int off = 16; off > 0; off >>= 1) {
        kmax = umax(kmax, __shfl_down_sync(0xFFFFFFFFu, kmax, off));
        smax = fmaxf(smax, __shfl_down_sync(0xFFFFFFFFu, smax, off));
    }
    if (lane == 0) { wk[wid] = kmax; wm[wid] = smax; }
    __syncthreads();
    if (wid == 0) {
        unsigned km = (lane < 8) ? wk[lane] : 0u;
        float mm = (lane < 8) ? wm[lane] : NEG_INF;
#pragma unroll
        for (int off = 4; off > 0; off >>= 1) {
            km = umax(km, __shfl_down_sync(0xFFFFFFFFu, km, off));
            mm = fmaxf(mm, __shfl_down_sync(0xFFFFFFFFu, mm, off));
        }
        if (lane == 0) { s_key1 = km; s_max = mm; }
    }
    __syncthreads();

    // phase 2: second-best key (mask exact winner), for refinement trigger
    unsigned key1 = s_key1;
    unsigned k2 = 0u;
#pragma unroll
    for (int jj = 0; jj < 4; jj++)
        k2 = umax(k2, (keys[jj] == key1) ? 0u : keys[jj]);
#pragma unroll
    for (int off = 16; off > 0; off >>= 1)
        k2 = umax(k2, __shfl_down_sync(0xFFFFFFFFu, k2, off));
    if (lane == 0) wk[wid] = k2;
    __syncthreads();
    if (wid == 0) {
        unsigned km = (lane < 8) ? wk[lane] : 0u;
#pragma unroll
        for (int off = 4; off > 0; off >>= 1)
            km = umax(km, __shfl_down_sync(0xFFFFFFFFu, km, off));
        if (lane == 0) s_key2 = km;
    }
    __syncthreads();

    float gapq = ykey_val(s_key1) - ykey_val(s_key2);
    int bidx = 1023 - (int)(s_key1 & 1023u);

    // rare refinement: exact-gumbel top-3 over register svv, then fp64 decision
    if (gapq < 0.03f) {
        float v1 = NEG_INF, v2 = NEG_INF, v3 = NEG_INF;
        int   i1 = IMAX, i2 = IMAX, i3 = IMAX;
#pragma unroll
        for (int jj = 0; jj < 4; jj++) {
            int k = t * 4 + jj;
            float y = svv[jj] + gumbel_exact(ebase + (unsigned)jj);
            ins3(y, k, v1, i1, v2, i2, v3, i3);
        }
#pragma unroll
        for (int off = 16; off > 0; off >>= 1) {
            float b1 = __shfl_down_sync(0xFFFFFFFFu, v1, off);
            int  bi1 = __shfl_down_sync(0xFFFFFFFFu, i1, off);
            float b2 = __shfl_down_sync(0xFFFFFFFFu, v2, off);
            int  bi2 = __shfl_down_sync(0xFFFFFFFFu, i2, off);
            float b3 = __shfl_down_sync(0xFFFFFFFFu, v3, off);
            int  bi3 = __shfl_down_sync(0xFFFFFFFFu, i3, off);
            ins3(b1, bi1, v1, i1, v2, i2, v3, i3);
            ins3(b2, bi2, v1, i1, v2, i2, v3, i3);
            ins3(b3, bi3, v1, i1, v2, i2, v3, i3);
        }
        // reuse rd1 as staging for per-warp top-3 (as 3 floats + 3 ints packed)
        __shared__ float rv1[8], rv2[8], rv3[8];
        __shared__ int   ri1[8], ri2[8], ri3[8];
        if (lane == 0) { rv1[wid] = v1; ri1[wid] = i1; rv2[wid] = v2; ri2[wid] = i2; rv3[wid] = v3; ri3[wid] = i3; }
        __syncthreads();
        if (wid == 0) {
            float a1 = (lane < 8) ? rv1[lane] : NEG_INF;
            int  ai1 = (lane < 8) ? ri1[lane] : IMAX;
            float a2 = (lane < 8) ? rv2[lane] : NEG_INF;
            int  ai2 = (lane < 8) ? ri2[lane] : IMAX;
            float a3 = (lane < 8) ? rv3[lane] : NEG_INF;
            int  ai3 = (lane < 8) ? ri3[lane] : IMAX;
#pragma unroll
            for (int off = 4; off > 0; off >>= 1) {
                float b1 = __shfl_down_sync(0xFFFFFFFFu, a1, off);
                int  bi1 = __shfl_down_sync(0xFFFFFFFFu, ai1, off);
                float b2 = __shfl_down_sync(0xFFFFFFFFu, a2, off);
                int  bi2 = __shfl_down_sync(0xFFFFFFFFu, ai2, off);
                float b3 = __shfl_down_sync(0xFFFFFFFFu, a3, off);
                int  bi3 = __shfl_down_sync(0xFFFFFFFFu, ai3, off);
                ins3(b1, bi1, a1, ai1, a2, ai2, a3, ai3);
                ins3(b2, bi2, a1, ai1, a2, ai2, a3, ai3);
                ins3(b3, bi3, a1, ai1, a2, ai2, a3, ai3);
            }
            if (lane == 0) { s_i1 = ai1; s_i2 = ai2; s_i3 = ai3; }
        }
        __syncthreads();

        // fp64 + exact-gumbel decision over top-3
        int b = n >> 10, hw = n & 1023;
        float xd = inp[(size_t)b * (DDIM * HWSZ) + (size_t)t * HWSZ + hw];
        float e1 = emb[(size_t)s_i1 * DDIM + t];
        float e2 = emb[(size_t)s_i2 * DDIM + t];
        float e3 = emb[(size_t)s_i3 * DDIM + t];
        rd1[t] = 2.0 * (double)xd * (double)e1 - (double)e1 * (double)e1;
        rd2[t] = 2.0 * (double)xd * (double)e2 - (double)e2 * (double)e2;
        rd3[t] = 2.0 * (double)xd * (double)e3 - (double)e3 * (double)e3;
        __syncthreads();
        for (int off = 128; off > 0; off >>= 1) {
            if (t < off) { rd1[t] += rd1[t + off]; rd2[t] += rd2[t + off]; rd3[t] += rd3[t + off]; }
            __syncthreads();
        }
        if (t == 0) {
            double ya = rd1[0] + (double)gumbel_exact((unsigned)n * (unsigned)KCODES + (unsigned)s_i1);
            double yb = rd2[0] + (double)gumbel_exact((unsigned)n * (unsigned)KCODES + (unsigned)s_i2);
            double yc = rd3[0] + (double)gumbel_exact((unsigned)n * (unsigned)KCODES + (unsigned)s_i3);
            double bv = ya; int bi = s_i1;
            if (yb > bv || (yb == bv && s_i2 < bi)) { bv = yb; bi = s_i2; }
            if (yc > bv || (yc == bv && s_i3 < bi)) { bv = yc; bi = s_i3; }
            bidx = bi;
        }
        __syncthreads();
    }

    // phase 3: entropy
    float mrow = s_max;
    float z = 0.0f, w = 0.0f;
#pragma unroll
    for (int jj = 0; jj < 4; jj++) {
        float d = svv[jj] - mrow;
        float e = __expf(d);
        z += e;
        w += d * e;
    }
#pragma unroll
    for (int off = 16; off > 0; off >>= 1) {
        z += __shfl_down_sync(0xFFFFFFFFu, z, off);
        w += __shfl_down_sync(0xFFFFFFFFu, w, off);
    }
    if (lane == 0) { wz[wid] = z; ww[wid] = w; }
    __syncthreads();
    if (t == 0) {
        float Z = 0.0f, W = 0.0f;
#pragma unroll
        for (int q = 0; q < 8; q++) { Z += wz[q]; W += ww[q]; }
        g_entrow[n] = W / Z - logf(Z);
        g_idx[n] = bidx;
        atomicAdd(&g_counts[bidx], 1.0f);
    }
}

// ---------------- kernel 5: scatter q_out = embedding[idx] ----------------
__global__ __launch_bounds__(256)
void scatter_kernel(const float* __restrict__ E, float* __restrict__ qout) {
    int b  = blockIdx.y;
    int hw = blockIdx.x * 256 + threadIdx.x;
    int n  = b * HWSZ + hw;
    int row = g_idx[n];
    const float4* e4 = reinterpret_cast<const float4*>(E + (size_t)row * DDIM);
    float* outb = qout + (size_t)b * (DDIM * HWSZ) + hw;
#pragma unroll 4
    for (int d4 = 0; d4 < DDIM / 4; d4++) {
        float4 v = e4[d4];
        outb[(size_t)(d4 * 4 + 0) * HWSZ] = v.x;
        outb[(size_t)(d4 * 4 + 1) * HWSZ] = v.y;
        outb[(size_t)(d4 * 4 + 2) * HWSZ] = v.z;
        outb[(size_t)(d4 * 4 + 3) * HWSZ] = v.w;
    }
}

// ---------------- kernel 6: finalize ----------------
__global__ __launch_bounds__(1024)
void finalize_kernel(float* __restrict__ out) {
    __shared__ double sh1[1024];
    __shared__ double sh2[1024];
    int t = threadIdx.x;
    double es = 0.0;
    for (int j = 0; j < NROWS / 1024; j++) es += (double)g_entrow[t + 1024 * j];
    float c = g_counts[t];
    float q = c * (1.0f / (float)NROWS);
    float term = q * logf(q + 1e-10f);
    sh1[t] = es;
    sh2[t] = (double)term;
    __syncthreads();
    for (int off = 512; off > 0; off >>= 1) {
        if (t < off) { sh1[t] += sh1[t + off]; sh2[t] += sh2[t + off]; }
        __syncthreads();
    }
    if (t == 0) {
        out[0] = 0.25f * (float)(sh1[0] / (double)NROWS);
        out[1 + QELEMS] = expf(-(float)sh2[0]);
    }
}

// ---------------- launch: single stream ----------------
extern "C" void kernel_launch(void* const* d_in, const int* in_sizes, int n_in,
                              void* d_out, int out_size) {
    const float* inp = (const float*)d_in[0];
    const float* emb = (const float*)d_in[1];
    float* out = (float*)d_out;

    cudaFuncSetAttribute(gemm_f16_kernel, cudaFuncAttributeMaxDynamicSharedMemorySize, SMEM_DYN);

    transpose_kernel<<<dim3(HWSZ / 32, DDIM / 32, BATCH), dim3(32, 8)>>>(inp);
    prep_e_kernel<<<KCODES, 256>>>(emb);
    gemm_f16_kernel<<<dim3(KCODES / 128, NROWS / 128), 256, SMEM_DYN>>>();
    epi_kernel<<<NROWS, 256>>>(inp, emb);
    scatter_kernel<<<dim3(HWSZ / 256, BATCH), 256>>>(emb, out + 1);
    finalize_kernel<<<1, 1024>>>(out);
}

// round 15
// speedup vs baseline: 1.6915x; 1.0280x over previous
#include <cuda_runtime.h>
#include <cuda_fp16.h>
#include <math.h>
#include <stdint.h>

// N = 64*32*32 = 65536 rows, D = 256, K = 1024
// Output layout: [loss (1), q_out (16777216), perplexity (1)]

#define NROWS   65536
#define DDIM    256
#define KCODES  1024
#define BATCH   64
#define HWSZ    1024
#define QELEMS  16777216

#define NEG_INF (-__int_as_float(0x7f800000))
#define IMAX    0x7FFFFFFF
#define JAX_PARTITIONABLE 1

// ---------------- scratch (device globals; no allocation allowed) ----------------
__device__ __half g_Xh[(size_t)NROWS * DDIM];          // fp16(x)     (32 MB)
__device__ __half g_Eh[(size_t)KCODES * DDIM];
__device__ __half g_Sh[(size_t)NROWS * KCODES];        // logits fp16 (128 MB)
__device__ float g_bnorm[KCODES];
__device__ float g_counts[KCODES];
__device__ float g_entrow[NROWS];
__device__ int   g_idx[NROWS];

// ---------------- helpers ----------------
__device__ __forceinline__ uint32_t smem_u32(const void* p) {
    uint32_t a;
    asm("{ .reg .u64 t; cvta.to.shared.u64 t, %1; cvt.u32.u64 %0, t; }" : "=r"(a) : "l"(p));
    return a;
}
__device__ __forceinline__ void ldsm4(uint32_t* r, const void* p) {
    uint32_t addr = smem_u32(p);
    asm volatile("ldmatrix.sync.aligned.m8n8.x4.shared.b16 {%0,%1,%2,%3}, [%4];"
        : "=r"(r[0]), "=r"(r[1]), "=r"(r[2]), "=r"(r[3]) : "r"(addr));
}
__device__ __forceinline__ void mma_f16(float* c, const uint32_t* a, uint32_t b0, uint32_t b1) {
    asm("mma.sync.aligned.m16n8k16.row.col.f32.f16.f16.f32 "
        "{%0,%1,%2,%3}, {%4,%5,%6,%7}, {%8,%9}, {%0,%1,%2,%3};"
        : "+f"(c[0]), "+f"(c[1]), "+f"(c[2]), "+f"(c[3])
        : "r"(a[0]), "r"(a[1]), "r"(a[2]), "r"(a[3]), "r"(b0), "r"(b1));
}
__device__ __forceinline__ void cpa16(uint32_t s, const void* g) {
    asm volatile("cp.async.ca.shared.global [%0], [%1], 16;" :: "r"(s), "l"(g));
}
#define CPA_COMMIT() asm volatile("cp.async.commit_group;" ::: "memory")
#define CPA_WAIT1()  asm volatile("cp.async.wait_group 1;" ::: "memory")

// ---------------- threefry2x32 (JAX-exact, validated R4/R6-R14) ----------------
__device__ __forceinline__ void threefry2x32(unsigned int x0, unsigned int x1,
                                             unsigned int& r0, unsigned int& r1) {
    const unsigned int k0 = 0u, k1 = 42u;
    const unsigned int k2 = 0u ^ 42u ^ 0x1BD11BDAu;
#define TFR(r) { x0 += x1; x1 = __funnelshift_l(x1, x1, r); x1 ^= x0; }
    x0 += k0; x1 += k1;
    TFR(13) TFR(15) TFR(26) TFR(6)
    x0 += k1; x1 += k2 + 1u;
    TFR(17) TFR(29) TFR(16) TFR(24)
    x0 += k2; x1 += k0 + 2u;
    TFR(13) TFR(15) TFR(26) TFR(6)
    x0 += k0; x1 += k1 + 3u;
    TFR(17) TFR(29) TFR(16) TFR(24)
    x0 += k1; x1 += k2 + 4u;
    TFR(13) TFR(15) TFR(26) TFR(6)
    x0 += k2; x1 += k0 + 5u;
#undef TFR
    r0 = x0; r1 = x1;
}
__device__ __forceinline__ unsigned int rbits_at(unsigned int e) {
#if JAX_PARTITIONABLE
    unsigned int r0, r1;
    threefry2x32(0u, e, r0, r1);
    return r0 ^ r1;
#else
    const unsigned int NH = (NROWS * (unsigned)KCODES) / 2u;
    unsigned int p = (e < NH) ? e : (e - NH);
    unsigned int r0, r1;
    threefry2x32(p, p + NH, r0, r1);
    return (e < NH) ? r0 : r1;
#endif
}
// exact version: reference-grade (refinement only; bit-matched 8 passing rounds)
__device__ __forceinline__ float gumbel_exact(unsigned int e) {
    unsigned int bits = rbits_at(e);
    float f = __uint_as_float((bits >> 9) | 0x3f800000u) - 1.0f;
    float u = fmaxf(1e-9f, f + 1e-9f);
    return -logf(-logf(u));
}
// scan version: branchless, ~1e-4 abs accuracy; covered by refinement window.
__device__ __forceinline__ float gumbel_scan(unsigned int e) {
    unsigned int bits = rbits_at(e);
    float f = __uint_as_float((bits >> 9) | 0x3f800000u) - 1.0f;  // [0,1), exact
    float u = f + 1e-9f;
    float w_fast = -__log2f(u);
    float dd = (1.0f - f) - 1e-9f;
    float w_ser = dd * fmaf(dd, fmaf(dd, 0.48089835f, 0.72134752f), 1.4426950f);
    float w = (f > 0.996f) ? w_ser : w_fast;
    return fmaf(-0.69314718f, __log2f(w), 0.36651292f);   // -ln(ln2*w)
}

// ---------------- ordered-float key pack/unpack ----------------
__device__ __forceinline__ unsigned ykey(float y, int k) {
    int b = __float_as_int(y);
    unsigned ob = (unsigned)(b ^ ((b >> 31) | 0x80000000));
    return (ob & 0xFFFFFC00u) | (1023u - (unsigned)k);
}
__device__ __forceinline__ float ykey_val(unsigned key) {
    unsigned ob = key & 0xFFFFFC00u;
    int b = (ob & 0x80000000u) ? (int)(ob ^ 0x80000000u) : (int)~ob;
    return __int_as_float(b);
}

// ---------------- kernel 1: transpose + fp16 convert ----------------
__global__ void transpose_kernel(const float* __restrict__ in) {
    __shared__ float tile[32][33];
    int b   = blockIdx.z;
    int hw0 = blockIdx.x * 32;
    int d0  = blockIdx.y * 32;
    int tx = threadIdx.x, ty = threadIdx.y;
    const float* src = in + (size_t)b * (DDIM * HWSZ);
#pragma unroll
    for (int j = 0; j < 4; j++) {
        int d  = d0 + ty + j * 8;
        int hw = hw0 + tx;
        tile[ty + j * 8][tx] = src[(size_t)d * HWSZ + hw];
    }
    __syncthreads();
#pragma unroll
    for (int j = 0; j < 4; j++) {
        int hw = hw0 + ty + j * 8;
        int d  = d0 + tx;
        g_Xh[(size_t)(b * HWSZ + hw) * DDIM + d] = __float2half_rn(tile[tx][ty + j * 8]);
    }
}

// ---------------- kernel 2: embedding norms + fp16 + zero counts ----------------
__global__ void prep_e_kernel(const float* __restrict__ E) {
    __shared__ float red[256];
    int k = blockIdx.x, t = threadIdx.x;
    float v = E[(size_t)k * DDIM + t];
    g_Eh[(size_t)k * DDIM + t] = __float2half_rn(v);
    red[t] = v * v;
    __syncthreads();
    for (int off = 128; off > 0; off >>= 1) {
        if (t < off) red[t] += red[t + off];
        __syncthreads();
    }
    if (t == 0) { g_bnorm[k] = red[0]; g_counts[k] = 0.0f; }
}

// ---------------- kernel 3: fp16 mma.sync GEMM, cp.async 3-stage, fp16 S out ----------------
#define LDS_ROW 40
#define TILE_ELEMS (128 * LDS_ROW)
#define TILE_BYTES (TILE_ELEMS * 2)
#define NSTAGE 3
#define SMEM_DYN (512 + NSTAGE * 2 * TILE_BYTES)    // 61952

__device__ __forceinline__ void issue_stage(uint32_t s_tiles_u32, int buf, int m0, int n0, int d0) {
    int tid = threadIdx.x;
    uint32_t base = s_tiles_u32 + (uint32_t)buf * 2 * TILE_BYTES;
#pragma unroll
    for (int q = 0; q < 2; q++) {
        int idx = tid + 256 * q;
        int row = idx >> 2, quad = idx & 3;
        uint32_t soff = (uint32_t)(row * LDS_ROW + quad * 8) * 2;
        size_t ga = (size_t)(m0 + row) * DDIM + d0 + quad * 8;
        size_t gb = (size_t)(n0 + row) * DDIM + d0 + quad * 8;
        cpa16(base + 0 * TILE_BYTES + soff, g_Xh + ga);
        cpa16(base + 1 * TILE_BYTES + soff, g_Eh + gb);
    }
}

__global__ __launch_bounds__(256, 2) void gemm_f16_kernel() {
    extern __shared__ char smem[];
    float* s_bn = (float*)smem;
    __half* s_tiles = (__half*)(smem + 512);
    uint32_t s_tiles_u32 = smem_u32(s_tiles);
#define TILE_PTR(st, a) (s_tiles + ((st) * 2 + (a)) * TILE_ELEMS)

    int tid = threadIdx.x, wid = tid >> 5, lane = tid & 31;
    int warp_m = wid & 3, warp_n = wid >> 2;
    int n0 = blockIdx.x * 128;
    int m0 = blockIdx.y * 128;

    if (tid < 128) s_bn[tid] = g_bnorm[n0 + tid];

    float acc[2][8][4];
#pragma unroll
    for (int i = 0; i < 2; i++)
#pragma unroll
        for (int j = 0; j < 8; j++)
#pragma unroll
            for (int q = 0; q < 4; q++) acc[i][j][q] = 0.0f;

    issue_stage(s_tiles_u32, 0, m0, n0, 0);
    CPA_COMMIT();
    issue_stage(s_tiles_u32, 1, m0, n0, 32);
    CPA_COMMIT();

    int a_row = warp_m * 32 + (lane & 15);
    int b_row = warp_n * 64 + (lane & 15);
    int k_off = (lane >> 4) * 8;

    for (int c = 0; c < 8; c++) {
        CPA_WAIT1();
        __syncthreads();
        if (c + 2 < 8) {
            issue_stage(s_tiles_u32, (c + 2) % NSTAGE, m0, n0, (c + 2) * 32);
            CPA_COMMIT();
        }
        int st = c % NSTAGE;
        const __half* At = TILE_PTR(st, 0);
        const __half* Bt = TILE_PTR(st, 1);
#pragma unroll
        for (int ks = 0; ks < 2; ks++) {
            int kc = ks * 16 + k_off;
            uint32_t fA[2][4];
#pragma unroll
            for (int mt = 0; mt < 2; mt++)
                ldsm4(fA[mt], At + (a_row + mt * 16) * LDS_ROW + kc);
#pragma unroll
            for (int bt = 0; bt < 4; bt++) {
                uint32_t fB[4];
                ldsm4(fB, Bt + (b_row + bt * 16) * LDS_ROW + kc);
                mma_f16(acc[0][2 * bt],     fA[0], fB[0], fB[2]);
                mma_f16(acc[1][2 * bt],     fA[1], fB[0], fB[2]);
                mma_f16(acc[0][2 * bt + 1], fA[0], fB[1], fB[3]);
                mma_f16(acc[1][2 * bt + 1], fA[1], fB[1], fB[3]);
            }
        }
    }

    // epilogue: s = 2*acc - bnorm -> fp16
    int g = lane >> 2, tg = lane & 3;
#pragma unroll
    for (int mi = 0; mi < 2; mi++) {
        int r0 = m0 + warp_m * 32 + mi * 16 + g;
#pragma unroll
        for (int ni = 0; ni < 8; ni++) {
            int cl = warp_n * 64 + ni * 8 + tg * 2;
            float bn0 = s_bn[cl], bn1 = s_bn[cl + 1];
            float2 o0 = { fmaf(2.0f, acc[mi][ni][0], -bn0), fmaf(2.0f, acc[mi][ni][1], -bn1) };
            float2 o1 = { fmaf(2.0f, acc[mi][ni][2], -bn0), fmaf(2.0f, acc[mi][ni][3], -bn1) };
            *(__half2*)&g_Sh[(size_t)r0 * KCODES + n0 + cl] = __float22half2_rn(o0);
            *(__half2*)&g_Sh[(size_t)(r0 + 8) * KCODES + n0 + cl] = __float22half2_rn(o1);
        }
    }
#undef TILE_PTR
}

// ---------------- top-3 insert (rare refine path only) ----------------
__device__ __forceinline__ void ins3(float v, int i,
                                     float& v1, int& i1, float& v2, int& i2, float& v3, int& i3) {
    if (v > v1 || (v == v1 && i < i1))      { v3 = v2; i3 = i2; v2 = v1; i2 = i1; v1 = v; i1 = i; }
    else if (v > v2 || (v == v2 && i < i2)) { v3 = v2; i3 = i2; v2 = v; i2 = i; }
    else if (v > v3 || (v == v3 && i < i3)) { v3 = v; i3 = i; }
}

// ---------------- kernel 4: fused entropy + packed-key top-2 gumbel argmax ----------------
__global__ __launch_bounds__(256)
void epi_kernel(const float* __restrict__ inp, const float* __restrict__ emb) {
    int n = blockIdx.x;
    int t = threadIdx.x;
    int lane = t & 31, wid = t >> 5;

    uint2 u2 = ((const uint2*)(g_Sh + (size_t)n * KCODES))[t];
    float2 f0 = __half22float2(*(__half2*)&u2.x);
    float2 f1 = __half22float2(*(__half2*)&u2.y);
    float svv[4] = {f0.x, f0.y, f1.x, f1.y};

    unsigned ebase = (unsigned)n * (unsigned)KCODES + (unsigned)t * 4u;
    // fused scan: top-2 packed keys + unnormalized softmax stats (|s| <= ~36, no overflow)
    unsigned k1 = 0u, k2 = 0u;
    float z = 0.0f, w = 0.0f;
#pragma unroll
    for (int jj = 0; jj < 4; jj++) {
        float y = svv[jj] + gumbel_scan(ebase + (unsigned)jj);
        unsigned key = ykey(y, t * 4 + jj);
        k2 = umax(k2, umin(k1, key));
        k1 = umax(k1, key);
        float e = __expf(svv[jj]);
        z += e;
        w += svv[jj] * e;
    }

    __shared__ unsigned wk1[8], wk2[8];
    __shared__ float wz[8], ww[8];
    __shared__ unsigned s_key1, s_key2;
    __shared__ float s_Z, s_W;
    __shared__ int   s_i1, s_i2, s_i3;
    __shared__ double rd1[256], rd2[256], rd3[256];

    // single warp reduction: top-2 keys + z + w
#pragma unroll
    for (int off = 16; off > 0; off >>= 1) {
        unsigned b1 = __shfl_down_sync(0xFFFFFFFFu, k1, off);
        unsigned b2 = __shfl_down_sync(0xFFFFFFFFu, k2, off);
        z += __shfl_down_sync(0xFFFFFFFFu, z, off);
        w += __shfl_down_sync(0xFFFFFFFFu, w, off);
        k2 = umax(umin(k1, b1), umax(k2, b2));
        k1 = umax(k1, b1);
    }
    if (lane == 0) { wk1[wid] = k1; wk2[wid] = k2; wz[wid] = z; ww[wid] = w; }
    __syncthreads();
    if (wid == 0) {
        unsigned a1 = (lane < 8) ? wk1[lane] : 0u;
        unsigned a2 = (lane < 8) ? wk2[lane] : 0u;
        float az = (lane < 8) ? wz[lane] : 0.0f;
        float aw = (lane < 8) ? ww[lane] : 0.0f;
#pragma unroll
        for (int off = 4; off > 0; off >>= 1) {
            unsigned b1 = __shfl_down_sync(0xFFFFFFFFu, a1, off);
            unsigned b2 = __shfl_down_sync(0xFFFFFFFFu, a2, off);
            az += __shfl_down_sync(0xFFFFFFFFu, az, off);
            aw += __shfl_down_sync(0xFFFFFFFFu, aw, off);
            a2 = umax(umin(a1, b1), umax(a2, b2));
            a1 = umax(a1, b1);
        }
        if (lane == 0) { s_key1 = a1; s_key2 = a2; s_Z = az; s_W = aw; }
    }
    __syncthreads();

    float gapq = ykey_val(s_key1) - ykey_val(s_key2);
    int bidx = 1023 - (int)(s_key1 & 1023u);

    // rare refinement: exact-gumbel top-3 over register svv, then fp64 decision
    if (gapq < 0.03f) {
        float v1 = NEG_INF, v2 = NEG_INF, v3 = NEG_INF;
        int   i1 = IMAX, i2 = IMAX, i3 = IMAX;
#pragma unroll
        for (int jj = 0; jj < 4; jj++) {
            int k = t * 4 + jj;
            float y = svv[jj] + gumbel_exact(ebase + (unsigned)jj);
            ins3(y, k, v1, i1, v2, i2, v3, i3);
        }
#pragma unroll
        for (int off = 16; off > 0; off >>= 1) {
            float b1 = __shfl_down_sync(0xFFFFFFFFu, v1, off);
            int  bi1 = __shfl_down_sync(0xFFFFFFFFu, i1, off);
            float b2 = __shfl_down_sync(0xFFFFFFFFu, v2, off);
            int  bi2 = __shfl_down_sync(0xFFFFFFFFu, i2, off);
            float b3 = __shfl_down_sync(0xFFFFFFFFu, v3, off);
            int  bi3 = __shfl_down_sync(0xFFFFFFFFu, i3, off);
            ins3(b1, bi1, v1, i1, v2, i2, v3, i3);
            ins3(b2, bi2, v1, i1, v2, i2, v3, i3);
            ins3(b3, bi3, v1, i1, v2, i2, v3, i3);
        }
        __shared__ float rv1[8], rv2[8], rv3[8];
        __shared__ int   ri1[8], ri2[8], ri3[8];
        if (lane == 0) { rv1[wid] = v1; ri1[wid] = i1; rv2[wid] = v2; ri2[wid] = i2; rv3[wid] = v3; ri3[wid] = i3; }
        __syncthreads();
        if (wid == 0) {
            float a1 = (lane < 8) ? rv1[lane] : NEG_INF;
            int  ai1 = (lane < 8) ? ri1[lane] : IMAX;
            float a2 = (lane < 8) ? rv2[lane] : NEG_INF;
            int  ai2 = (lane < 8) ? ri2[lane] : IMAX;
            float a3 = (lane < 8) ? rv3[lane] : NEG_INF;
            int  ai3 = (lane < 8) ? ri3[lane] : IMAX;
#pragma unroll
            for (int off = 4; off > 0; off >>= 1) {
                float b1 = __shfl_down_sync(0xFFFFFFFFu, a1, off);
                int  bi1 = __shfl_down_sync(0xFFFFFFFFu, ai1, off);
                float b2 = __shfl_down_sync(0xFFFFFFFFu, a2, off);
                int  bi2 = __shfl_down_sync(0xFFFFFFFFu, ai2, off);
                float b3 = __shfl_down_sync(0xFFFFFFFFu, a3, off);
                int  bi3 = __shfl_down_sync(0xFFFFFFFFu, ai3, off);
                ins3(b1, bi1, a1, ai1, a2, ai2, a3, ai3);
                ins3(b2, bi2, a1, ai1, a2, ai2, a3, ai3);
                ins3(b3, bi3, a1, ai1, a2, ai2, a3, ai3);
            }
            if (lane == 0) { s_i1 = ai1; s_i2 = ai2; s_i3 = ai3; }
        }
        __syncthreads();

        int b = n >> 10, hw = n & 1023;
        float xd = inp[(size_t)b * (DDIM * HWSZ) + (size_t)t * HWSZ + hw];
        float e1 = emb[(size_t)s_i1 * DDIM + t];
        float e2 = emb[(size_t)s_i2 * DDIM + t];
        float e3 = emb[(size_t)s_i3 * DDIM + t];
        rd1[t] = 2.0 * (double)xd * (double)e1 - (double)e1 * (double)e1;
        rd2[t] = 2.0 * (double)xd * (double)e2 - (double)e2 * (double)e2;
        rd3[t] = 2.0 * (double)xd * (double)e3 - (double)e3 * (double)e3;
        __syncthreads();
        for (int off = 128; off > 0; off >>= 1) {
            if (t < off) { rd1[t] += rd1[t + off]; rd2[t] += rd2[t + off]; rd3[t] += rd3[t + off]; }
            __syncthreads();
        }
        if (t == 0) {
            double ya = rd1[0] + (double)gumbel_exact((unsigned)n * (unsigned)KCODES + (unsigned)s_i1);
            double yb = rd2[0] + (double)gumbel_exact((unsigned)n * (unsigned)KCODES + (unsigned)s_i2);
            double yc = rd3[0] + (double)gumbel_exact((unsigned)n * (unsigned)KCODES + (unsigned)s_i3);
            double bv = ya; int bi = s_i1;
            if (yb > bv || (yb == bv && s_i2 < bi)) { bv = yb; bi = s_i2; }
            if (yc > bv || (yc == bv && s_i3 < bi)) { bv = yc; bi = s_i3; }
            bidx = bi;
        }
        __syncthreads();
    }

    if (t == 0) {
        g_entrow[n] = s_W / s_Z - logf(s_Z);
        g_idx[n] = bidx;
        atomicAdd(&g_counts[bidx], 1.0f);
    }
}

// ---------------- kernel 5: scatter q_out = embedding[idx] ----------------
__global__ __launch_bounds__(256)
void scatter_kernel(const float* __restrict__ E, float* __restrict__ qout) {
    int b  = blockIdx.y;
    int hw = blockIdx.x * 256 + threadIdx.x;
    int n  = b * HWSZ + hw;
    int row = g_idx[n];
    const float4* e4 = reinterpret_cast<const float4*>(E + (size_t)row * DDIM);
    float* outb = qout + (size_t)b * (DDIM * HWSZ) + hw;
#pragma unroll 4
    for (int d4 = 0; d4 < DDIM / 4; d4++) {
        float4 v = e4[d4];
        outb[(size_t)(d4 * 4 + 0) * HWSZ] = v.x;
        outb[(size_t)(d4 * 4 + 1) * HWSZ] = v.y;
        outb[(size_t)(d4 * 4 + 2) * HWSZ] = v.z;
        outb[(size_t)(d4 * 4 + 3) * HWSZ] = v.w;
    }
}

// ---------------- kernel 6: finalize ----------------
__global__ __launch_bounds__(1024)
void finalize_kernel(float* __restrict__ out) {
    __shared__ double sh1[1024];
    __shared__ double sh2[1024];
    int t = threadIdx.x;
    double es = 0.0;
    for (int j = 0; j < NROWS / 1024; j++) es += (double)g_entrow[t + 1024 * j];
    float c = g_counts[t];
    float q = c * (1.0f / (float)NROWS);
    float term = q * logf(q + 1e-10f);
    sh1[t] = es;
    sh2[t] = (double)term;
    __syncthreads();
    for (int off = 512; off > 0; off >>= 1) {
        if (t < off) { sh1[t] += sh1[t + off]; sh2[t] += sh2[t + off]; }
        __syncthreads();
    }
    if (t == 0) {
        out[0] = 0.25f * (float)(sh1[0] / (double)NROWS);
        out[1 + QELEMS] = expf(-(float)sh2[0]);
    }
}

// ---------------- launch: single stream ----------------
extern "C" void kernel_launch(void* const* d_in, const int* in_sizes, int n_in,
                              void* d_out, int out_size) {
    const float* inp = (const float*)d_in[0];
    const float* emb = (const float*)d_in[1];
    float* out = (float*)d_out;

    cudaFuncSetAttribute(gemm_f16_kernel, cudaFuncAttributeMaxDynamicSharedMemorySize, SMEM_DYN);

    transpose_kernel<<<dim3(HWSZ / 32, DDIM / 32, BATCH), dim3(32, 8)>>>(inp);
    prep_e_kernel<<<KCODES, 256>>>(emb);
    gemm_f16_kernel<<<dim3(KCODES / 128, NROWS / 128), 256, SMEM_DYN>>>();
    epi_kernel<<<NROWS, 256>>>(inp, emb);
    scatter_kernel<<<dim3(HWSZ / 256, BATCH), 256>>>(emb, out + 1);
    finalize_kernel<<<1, 1024>>>(out);
}

// round 16
// speedup vs baseline: 1.8014x; 1.0650x over previous
#include <cuda_runtime.h>
#include <cuda_fp16.h>
#include <math.h>
#include <stdint.h>

// N = 64*32*32 = 65536 rows, D = 256, K = 1024
// Output layout: [loss (1), q_out (16777216), perplexity (1)]

#define NROWS   65536
#define DDIM    256
#define KCODES  1024
#define BATCH   64
#define HWSZ    1024
#define QELEMS  16777216

#define NEG_INF (-__int_as_float(0x7f800000))
#define IMAX    0x7FFFFFFF
#define JAX_PARTITIONABLE 1

// ---------------- scratch (device globals; no allocation allowed) ----------------
__device__ __half g_Xh[(size_t)NROWS * DDIM];          // fp16(x)     (32 MB)
__device__ __half g_Eh[(size_t)KCODES * DDIM];
__device__ __half g_Sh[(size_t)NROWS * KCODES];        // logits fp16 (128 MB)
__device__ float g_bnorm[KCODES];
__device__ float g_counts[KCODES];
__device__ float g_entrow[NROWS];
__device__ int   g_idx[NROWS];

// ---------------- helpers ----------------
__device__ __forceinline__ uint32_t smem_u32(const void* p) {
    uint32_t a;
    asm("{ .reg .u64 t; cvta.to.shared.u64 t, %1; cvt.u32.u64 %0, t; }" : "=r"(a) : "l"(p));
    return a;
}
__device__ __forceinline__ void ldsm4(uint32_t* r, const void* p) {
    uint32_t addr = smem_u32(p);
    asm volatile("ldmatrix.sync.aligned.m8n8.x4.shared.b16 {%0,%1,%2,%3}, [%4];"
        : "=r"(r[0]), "=r"(r[1]), "=r"(r[2]), "=r"(r[3]) : "r"(addr));
}
__device__ __forceinline__ void mma_f16(float* c, const uint32_t* a, uint32_t b0, uint32_t b1) {
    asm("mma.sync.aligned.m16n8k16.row.col.f32.f16.f16.f32 "
        "{%0,%1,%2,%3}, {%4,%5,%6,%7}, {%8,%9}, {%0,%1,%2,%3};"
        : "+f"(c[0]), "+f"(c[1]), "+f"(c[2]), "+f"(c[3])
        : "r"(a[0]), "r"(a[1]), "r"(a[2]), "r"(a[3]), "r"(b0), "r"(b1));
}
__device__ __forceinline__ void cpa16(uint32_t s, const void* g) {
    asm volatile("cp.async.ca.shared.global [%0], [%1], 16;" :: "r"(s), "l"(g));
}
#define CPA_COMMIT() asm volatile("cp.async.commit_group;" ::: "memory")
#define CPA_WAIT1()  asm volatile("cp.async.wait_group 1;" ::: "memory")

// ---------------- threefry2x32 (JAX-exact, validated R4/R6-R15) ----------------
__device__ __forceinline__ void threefry2x32(unsigned int x0, unsigned int x1,
                                             unsigned int& r0, unsigned int& r1) {
    const unsigned int k0 = 0u, k1 = 42u;
    const unsigned int k2 = 0u ^ 42u ^ 0x1BD11BDAu;
#define TFR(r) { x0 += x1; x1 = __funnelshift_l(x1, x1, r); x1 ^= x0; }
    x0 += k0; x1 += k1;
    TFR(13) TFR(15) TFR(26) TFR(6)
    x0 += k1; x1 += k2 + 1u;
    TFR(17) TFR(29) TFR(16) TFR(24)
    x0 += k2; x1 += k0 + 2u;
    TFR(13) TFR(15) TFR(26) TFR(6)
    x0 += k0; x1 += k1 + 3u;
    TFR(17) TFR(29) TFR(16) TFR(24)
    x0 += k1; x1 += k2 + 4u;
    TFR(13) TFR(15) TFR(26) TFR(6)
    x0 += k2; x1 += k0 + 5u;
#undef TFR
    r0 = x0; r1 = x1;
}
__device__ __forceinline__ unsigned int rbits_at(unsigned int e) {
#if JAX_PARTITIONABLE
    unsigned int r0, r1;
    threefry2x32(0u, e, r0, r1);
    return r0 ^ r1;
#else
    const unsigned int NH = (NROWS * (unsigned)KCODES) / 2u;
    unsigned int p = (e < NH) ? e : (e - NH);
    unsigned int r0, r1;
    threefry2x32(p, p + NH, r0, r1);
    return (e < NH) ? r0 : r1;
#endif
}
// exact version: reference-grade (refinement only; bit-matched 9 passing rounds)
__device__ __forceinline__ float gumbel_exact(unsigned int e) {
    unsigned int bits = rbits_at(e);
    float f = __uint_as_float((bits >> 9) | 0x3f800000u) - 1.0f;
    float u = fmaxf(1e-9f, f + 1e-9f);
    return -logf(-logf(u));
}
// scan version: branchless, ~1e-4 abs accuracy; covered by refinement window.
__device__ __forceinline__ float gumbel_scan(unsigned int e) {
    unsigned int bits = rbits_at(e);
    float f = __uint_as_float((bits >> 9) | 0x3f800000u) - 1.0f;  // [0,1), exact
    float u = f + 1e-9f;
    float w_fast = -__log2f(u);
    float dd = (1.0f - f) - 1e-9f;
    float w_ser = dd * fmaf(dd, fmaf(dd, 0.48089835f, 0.72134752f), 1.4426950f);
    float w = (f > 0.996f) ? w_ser : w_fast;
    return fmaf(-0.69314718f, __log2f(w), 0.36651292f);   // -ln(ln2*w)
}

// ---------------- ordered-float key pack/unpack ----------------
__device__ __forceinline__ unsigned ykey(float y, int k) {
    int b = __float_as_int(y);
    unsigned ob = (unsigned)(b ^ ((b >> 31) | 0x80000000));
    return (ob & 0xFFFFFC00u) | (1023u - (unsigned)k);
}
__device__ __forceinline__ float ykey_val(unsigned key) {
    unsigned ob = key & 0xFFFFFC00u;
    int b = (ob & 0x80000000u) ? (int)(ob ^ 0x80000000u) : (int)~ob;
    return __int_as_float(b);
}

// ---------------- kernel 1: transpose + fp16 convert ----------------
__global__ void transpose_kernel(const float* __restrict__ in) {
    __shared__ float tile[32][33];
    int b   = blockIdx.z;
    int hw0 = blockIdx.x * 32;
    int d0  = blockIdx.y * 32;
    int tx = threadIdx.x, ty = threadIdx.y;
    const float* src = in + (size_t)b * (DDIM * HWSZ);
#pragma unroll
    for (int j = 0; j < 4; j++) {
        int d  = d0 + ty + j * 8;
        int hw = hw0 + tx;
        tile[ty + j * 8][tx] = src[(size_t)d * HWSZ + hw];
    }
    __syncthreads();
#pragma unroll
    for (int j = 0; j < 4; j++) {
        int hw = hw0 + ty + j * 8;
        int d  = d0 + tx;
        g_Xh[(size_t)(b * HWSZ + hw) * DDIM + d] = __float2half_rn(tile[tx][ty + j * 8]);
    }
}

// ---------------- kernel 2: embedding norms + fp16 + zero counts ----------------
__global__ void prep_e_kernel(const float* __restrict__ E) {
    __shared__ float red[256];
    int k = blockIdx.x, t = threadIdx.x;
    float v = E[(size_t)k * DDIM + t];
    g_Eh[(size_t)k * DDIM + t] = __float2half_rn(v);
    red[t] = v * v;
    __syncthreads();
    for (int off = 128; off > 0; off >>= 1) {
        if (t < off) red[t] += red[t + off];
        __syncthreads();
    }
    if (t == 0) { g_bnorm[k] = red[0]; g_counts[k] = 0.0f; }
}

// ---------------- kernel 3: fp16 mma.sync GEMM, cp.async 3-stage, fp16 S out ----------------
#define LDS_ROW 40
#define TILE_ELEMS (128 * LDS_ROW)
#define TILE_BYTES (TILE_ELEMS * 2)
#define NSTAGE 3
#define SMEM_DYN (512 + NSTAGE * 2 * TILE_BYTES)    // 61952

__device__ __forceinline__ void issue_stage(uint32_t s_tiles_u32, int buf, int m0, int n0, int d0) {
    int tid = threadIdx.x;
    uint32_t base = s_tiles_u32 + (uint32_t)buf * 2 * TILE_BYTES;
#pragma unroll
    for (int q = 0; q < 2; q++) {
        int idx = tid + 256 * q;
        int row = idx >> 2, quad = idx & 3;
        uint32_t soff = (uint32_t)(row * LDS_ROW + quad * 8) * 2;
        size_t ga = (size_t)(m0 + row) * DDIM + d0 + quad * 8;
        size_t gb = (size_t)(n0 + row) * DDIM + d0 + quad * 8;
        cpa16(base + 0 * TILE_BYTES + soff, g_Xh + ga);
        cpa16(base + 1 * TILE_BYTES + soff, g_Eh + gb);
    }
}

__global__ __launch_bounds__(256, 2) void gemm_f16_kernel() {
    extern __shared__ char smem[];
    float* s_bn = (float*)smem;
    __half* s_tiles = (__half*)(smem + 512);
    uint32_t s_tiles_u32 = smem_u32(s_tiles);
#define TILE_PTR(st, a) (s_tiles + ((st) * 2 + (a)) * TILE_ELEMS)

    int tid = threadIdx.x, wid = tid >> 5, lane = tid & 31;
    int warp_m = wid & 3, warp_n = wid >> 2;
    int n0 = blockIdx.x * 128;
    int m0 = blockIdx.y * 128;

    if (tid < 128) s_bn[tid] = g_bnorm[n0 + tid];

    float acc[2][8][4];
#pragma unroll
    for (int i = 0; i < 2; i++)
#pragma unroll
        for (int j = 0; j < 8; j++)
#pragma unroll
            for (int q = 0; q < 4; q++) acc[i][j][q] = 0.0f;

    issue_stage(s_tiles_u32, 0, m0, n0, 0);
    CPA_COMMIT();
    issue_stage(s_tiles_u32, 1, m0, n0, 32);
    CPA_COMMIT();

    int a_row = warp_m * 32 + (lane & 15);
    int b_row = warp_n * 64 + (lane & 15);
    int k_off = (lane >> 4) * 8;

    for (int c = 0; c < 8; c++) {
        CPA_WAIT1();
        __syncthreads();
        if (c + 2 < 8) {
            issue_stage(s_tiles_u32, (c + 2) % NSTAGE, m0, n0, (c + 2) * 32);
            CPA_COMMIT();
        }
        int st = c % NSTAGE;
        const __half* At = TILE_PTR(st, 0);
        const __half* Bt = TILE_PTR(st, 1);
#pragma unroll
        for (int ks = 0; ks < 2; ks++) {
            int kc = ks * 16 + k_off;
            uint32_t fA[2][4];
#pragma unroll
            for (int mt = 0; mt < 2; mt++)
                ldsm4(fA[mt], At + (a_row + mt * 16) * LDS_ROW + kc);
#pragma unroll
            for (int bt = 0; bt < 4; bt++) {
                uint32_t fB[4];
                ldsm4(fB, Bt + (b_row + bt * 16) * LDS_ROW + kc);
                mma_f16(acc[0][2 * bt],     fA[0], fB[0], fB[2]);
                mma_f16(acc[1][2 * bt],     fA[1], fB[0], fB[2]);
                mma_f16(acc[0][2 * bt + 1], fA[0], fB[1], fB[3]);
                mma_f16(acc[1][2 * bt + 1], fA[1], fB[1], fB[3]);
            }
        }
    }

    // epilogue: s = 2*acc - bnorm -> fp16
    int g = lane >> 2, tg = lane & 3;
#pragma unroll
    for (int mi = 0; mi < 2; mi++) {
        int r0 = m0 + warp_m * 32 + mi * 16 + g;
#pragma unroll
        for (int ni = 0; ni < 8; ni++) {
            int cl = warp_n * 64 + ni * 8 + tg * 2;
            float bn0 = s_bn[cl], bn1 = s_bn[cl + 1];
            float2 o0 = { fmaf(2.0f, acc[mi][ni][0], -bn0), fmaf(2.0f, acc[mi][ni][1], -bn1) };
            float2 o1 = { fmaf(2.0f, acc[mi][ni][2], -bn0), fmaf(2.0f, acc[mi][ni][3], -bn1) };
            *(__half2*)&g_Sh[(size_t)r0 * KCODES + n0 + cl] = __float22half2_rn(o0);
            *(__half2*)&g_Sh[(size_t)(r0 + 8) * KCODES + n0 + cl] = __float22half2_rn(o1);
        }
    }
#undef TILE_PTR
}

// ---------------- top-3 insert (rare refine path only) ----------------
__device__ __forceinline__ void ins3(float v, int i,
                                     float& v1, int& i1, float& v2, int& i2, float& v3, int& i3) {
    if (v > v1 || (v == v1 && i < i1))      { v3 = v2; i3 = i2; v2 = v1; i2 = i1; v1 = v; i1 = i; }
    else if (v > v2 || (v == v2 && i < i2)) { v3 = v2; i3 = i2; v2 = v; i2 = i; }
    else if (v > v3 || (v == v3 && i < i3)) { v3 = v; i3 = i; }
}

// ---------------- kernel 4: fused entropy + packed-key top-2 gumbel argmax ----------------
// 128 threads/block, 8 elements/thread (one row per block)
__global__ __launch_bounds__(128)
void epi_kernel(const float* __restrict__ inp, const float* __restrict__ emb) {
    int n = blockIdx.x;
    int t = threadIdx.x;          // 0..127
    int lane = t & 31, wid = t >> 5;  // 4 warps

    uint4 u4 = ((const uint4*)(g_Sh + (size_t)n * KCODES))[t];
    float svv[8];
    {
        float2 a = __half22float2(*(__half2*)&u4.x);
        float2 b = __half22float2(*(__half2*)&u4.y);
        float2 c = __half22float2(*(__half2*)&u4.z);
        float2 d = __half22float2(*(__half2*)&u4.w);
        svv[0] = a.x; svv[1] = a.y; svv[2] = b.x; svv[3] = b.y;
        svv[4] = c.x; svv[5] = c.y; svv[6] = d.x; svv[7] = d.y;
    }

    unsigned ebase = (unsigned)n * (unsigned)KCODES + (unsigned)t * 8u;
    unsigned k1 = 0u, k2 = 0u;
    float z = 0.0f, w = 0.0f;
#pragma unroll
    for (int jj = 0; jj < 8; jj++) {
        float y = svv[jj] + gumbel_scan(ebase + (unsigned)jj);
        unsigned key = ykey(y, t * 8 + jj);
        k2 = umax(k2, umin(k1, key));
        k1 = umax(k1, key);
        float e = __expf(svv[jj]);
        z += e;
        w += svv[jj] * e;
    }

    __shared__ unsigned wk1[4], wk2[4];
    __shared__ float wz[4], ww[4];
    __shared__ unsigned s_key1, s_key2;
    __shared__ float s_Z, s_W;
    __shared__ int   s_i1, s_i2, s_i3;
    __shared__ double rd1[128], rd2[128], rd3[128];

#pragma unroll
    for (int off = 16; off > 0; off >>= 1) {
        unsigned b1 = __shfl_down_sync(0xFFFFFFFFu, k1, off);
        unsigned b2 = __shfl_down_sync(0xFFFFFFFFu, k2, off);
        z += __shfl_down_sync(0xFFFFFFFFu, z, off);
        w += __shfl_down_sync(0xFFFFFFFFu, w, off);
        k2 = umax(umin(k1, b1), umax(k2, b2));
        k1 = umax(k1, b1);
    }
    if (lane == 0) { wk1[wid] = k1; wk2[wid] = k2; wz[wid] = z; ww[wid] = w; }
    __syncthreads();
    if (wid == 0) {
        unsigned a1 = (lane < 4) ? wk1[lane] : 0u;
        unsigned a2 = (lane < 4) ? wk2[lane] : 0u;
        float az = (lane < 4) ? wz[lane] : 0.0f;
        float aw = (lane < 4) ? ww[lane] : 0.0f;
#pragma unroll
        for (int off = 2; off > 0; off >>= 1) {
            unsigned b1 = __shfl_down_sync(0xFFFFFFFFu, a1, off);
            unsigned b2 = __shfl_down_sync(0xFFFFFFFFu, a2, off);
            az += __shfl_down_sync(0xFFFFFFFFu, az, off);
            aw += __shfl_down_sync(0xFFFFFFFFu, aw, off);
            a2 = umax(umin(a1, b1), umax(a2, b2));
            a1 = umax(a1, b1);
        }
        if (lane == 0) { s_key1 = a1; s_key2 = a2; s_Z = az; s_W = aw; }
    }
    __syncthreads();

    float gapq = ykey_val(s_key1) - ykey_val(s_key2);
    int bidx = 1023 - (int)(s_key1 & 1023u);

    // rare refinement: exact-gumbel top-3 over register svv, then fp64 decision
    if (gapq < 0.03f) {
        float v1 = NEG_INF, v2 = NEG_INF, v3 = NEG_INF;
        int   i1 = IMAX, i2 = IMAX, i3 = IMAX;
#pragma unroll
        for (int jj = 0; jj < 8; jj++) {
            int k = t * 8 + jj;
            float y = svv[jj] + gumbel_exact(ebase + (unsigned)jj);
            ins3(y, k, v1, i1, v2, i2, v3, i3);
        }
#pragma unroll
        for (int off = 16; off > 0; off >>= 1) {
            float b1 = __shfl_down_sync(0xFFFFFFFFu, v1, off);
            int  bi1 = __shfl_down_sync(0xFFFFFFFFu, i1, off);
            float b2 = __shfl_down_sync(0xFFFFFFFFu, v2, off);
            int  bi2 = __shfl_down_sync(0xFFFFFFFFu, i2, off);
            float b3 = __shfl_down_sync(0xFFFFFFFFu, v3, off);
            int  bi3 = __shfl_down_sync(0xFFFFFFFFu, i3, off);
            ins3(b1, bi1, v1, i1, v2, i2, v3, i3);
            ins3(b2, bi2, v1, i1, v2, i2, v3, i3);
            ins3(b3, bi3, v1, i1, v2, i2, v3, i3);
        }
        __shared__ float rv1[4], rv2[4], rv3[4];
        __shared__ int   ri1[4], ri2[4], ri3[4];
        if (lane == 0) { rv1[wid] = v1; ri1[wid] = i1; rv2[wid] = v2; ri2[wid] = i2; rv3[wid] = v3; ri3[wid] = i3; }
        __syncthreads();
        if (wid == 0) {
            float a1 = (lane < 4) ? rv1[lane] : NEG_INF;
            int  ai1 = (lane < 4) ? ri1[lane] : IMAX;
            float a2 = (lane < 4) ? rv2[lane] : NEG_INF;
            int  ai2 = (lane < 4) ? ri2[lane] : IMAX;
            float a3 = (lane < 4) ? rv3[lane] : NEG_INF;
            int  ai3 = (lane < 4) ? ri3[lane] : IMAX;
#pragma unroll
            for (int off = 2; off > 0; off >>= 1) {
                float b1 = __shfl_down_sync(0xFFFFFFFFu, a1, off);
                int  bi1 = __shfl_down_sync(0xFFFFFFFFu, ai1, off);
                float b2 = __shfl_down_sync(0xFFFFFFFFu, a2, off);
                int  bi2 = __shfl_down_sync(0xFFFFFFFFu, ai2, off);
                float b3 = __shfl_down_sync(0xFFFFFFFFu, a3, off);
                int  bi3 = __shfl_down_sync(0xFFFFFFFFu, ai3, off);
                ins3(b1, bi1, a1, ai1, a2, ai2, a3, ai3);
                ins3(b2, bi2, a1, ai1, a2, ai2, a3, ai3);
                ins3(b3, bi3, a1, ai1, a2, ai2, a3, ai3);
            }
            if (lane == 0) { s_i1 = ai1; s_i2 = ai2; s_i3 = ai3; }
        }
        __syncthreads();

        // fp64 decision: each thread covers d = t and d = t + 128
        int b = n >> 10, hw = n & 1023;
        size_t xbase = (size_t)b * (DDIM * HWSZ) + hw;
        float xd0 = inp[xbase + (size_t)t * HWSZ];
        float xd1 = inp[xbase + (size_t)(t + 128) * HWSZ];
        float e1a = emb[(size_t)s_i1 * DDIM + t], e1b = emb[(size_t)s_i1 * DDIM + t + 128];
        float e2a = emb[(size_t)s_i2 * DDIM + t], e2b = emb[(size_t)s_i2 * DDIM + t + 128];
        float e3a = emb[(size_t)s_i3 * DDIM + t], e3b = emb[(size_t)s_i3 * DDIM + t + 128];
        rd1[t] = (2.0 * (double)xd0 * (double)e1a - (double)e1a * (double)e1a)
               + (2.0 * (double)xd1 * (double)e1b - (double)e1b * (double)e1b);
        rd2[t] = (2.0 * (double)xd0 * (double)e2a - (double)e2a * (double)e2a)
               + (2.0 * (double)xd1 * (double)e2b - (double)e2b * (double)e2b);
        rd3[t] = (2.0 * (double)xd0 * (double)e3a - (double)e3a * (double)e3a)
               + (2.0 * (double)xd1 * (double)e3b - (double)e3b * (double)e3b);
        __syncthreads();
        for (int off = 64; off > 0; off >>= 1) {
            if (t < off) { rd1[t] += rd1[t + off]; rd2[t] += rd2[t + off]; rd3[t] += rd3[t + off]; }
            __syncthreads();
        }
        if (t == 0) {
            double ya = rd1[0] + (double)gumbel_exact((unsigned)n * (unsigned)KCODES + (unsigned)s_i1);
            double yb = rd2[0] + (double)gumbel_exact((unsigned)n * (unsigned)KCODES + (unsigned)s_i2);
            double yc = rd3[0] + (double)gumbel_exact((unsigned)n * (unsigned)KCODES + (unsigned)s_i3);
            double bv = ya; int bi = s_i1;
            if (yb > bv || (yb == bv && s_i2 < bi)) { bv = yb; bi = s_i2; }
            if (yc > bv || (yc == bv && s_i3 < bi)) { bv = yc; bi = s_i3; }
            bidx = bi;
        }
        __syncthreads();
    }

    if (t == 0) {
        g_entrow[n] = s_W / s_Z - logf(s_Z);
        g_idx[n] = bidx;
        atomicAdd(&g_counts[bidx], 1.0f);
    }
}

// ---------------- kernel 5: scatter q_out = embedding[idx] ----------------
__global__ __launch_bounds__(256)
void scatter_kernel(const float* __restrict__ E, float* __restrict__ qout) {
    int b  = blockIdx.y;
    int hw = blockIdx.x * 256 + threadIdx.x;
    int n  = b * HWSZ + hw;
    int row = g_idx[n];
    const float4* e4 = reinterpret_cast<const float4*>(E + (size_t)row * DDIM);
    float* outb = qout + (size_t)b * (DDIM * HWSZ) + hw;
#pragma unroll 4
    for (int d4 = 0; d4 < DDIM / 4; d4++) {
        float4 v = e4[d4];
        outb[(size_t)(d4 * 4 + 0) * HWSZ] = v.x;
        outb[(size_t)(d4 * 4 + 1) * HWSZ] = v.y;
        outb[(size_t)(d4 * 4 + 2) * HWSZ] = v.z;
        outb[(size_t)(d4 * 4 + 3) * HWSZ] = v.w;
    }
}

// ---------------- kernel 6: finalize ----------------
__global__ __launch_bounds__(1024)
void finalize_kernel(float* __restrict__ out) {
    __shared__ double sh1[1024];
    __shared__ double sh2[1024];
    int t = threadIdx.x;
    double es = 0.0;
    for (int j = 0; j < NROWS / 1024; j++) es += (double)g_entrow[t + 1024 * j];
    float c = g_counts[t];
    float q = c * (1.0f / (float)NROWS);
    float term = q * logf(q + 1e-10f);
    sh1[t] = es;
    sh2[t] = (double)term;
    __syncthreads();
    for (int off = 512; off > 0; off >>= 1) {
        if (t < off) { sh1[t] += sh1[t + off]; sh2[t] += sh2[t + off]; }
        __syncthreads();
    }
    if (t == 0) {
        out[0] = 0.25f * (float)(sh1[0] / (double)NROWS);
        out[1 + QELEMS] = expf(-(float)sh2[0]);
    }
}

// ---------------- launch: single stream ----------------
extern "C" void kernel_launch(void* const* d_in, const int* in_sizes, int n_in,
                              void* d_out, int out_size) {
    const float* inp = (const float*)d_in[0];
    const float* emb = (const float*)d_in[1];
    float* out = (float*)d_out;

    cudaFuncSetAttribute(gemm_f16_kernel, cudaFuncAttributeMaxDynamicSharedMemorySize, SMEM_DYN);

    transpose_kernel<<<dim3(HWSZ / 32, DDIM / 32, BATCH), dim3(32, 8)>>>(inp);
    prep_e_kernel<<<KCODES, 256>>>(emb);
    gemm_f16_kernel<<<dim3(KCODES / 128, NROWS / 128), 256, SMEM_DYN>>>();
    epi_kernel<<<NROWS, 128>>>(inp, emb);
    scatter_kernel<<<dim3(HWSZ / 256, BATCH), 256>>>(emb, out + 1);
    finalize_kernel<<<1, 1024>>>(out);
}